// round 14
// baseline (speedup 1.0000x reference)
#include <cuda_runtime.h>
#include <cuda_bf16.h>
#include <cuda_fp16.h>
#include <math.h>

// Problem constants
#define MAXN 20000
#define MAXE 480000
#define C_POS 32
#define C_OUT 64
#define C_F   64
#define H1    256
#define H2    128

// ---------------- scratch ----------------
__device__ float g_Q [MAXN * C_OUT];
__device__ float g_K [MAXN * C_OUT];
__device__ float g_femb[MAXN * C_OUT];
__device__ __align__(16) unsigned g_YaH [MAXN * 128];   // half2-packed Ya  [N][128]
__device__ __align__(16) unsigned g_XFcH[MAXN * 128];   // half2-packed XFc [N][128]
__device__ float g_z[MAXE];
__device__ float g_denom[MAXN];
__device__ __align__(16) unsigned g_W1h[8 * H1 * 8];    // fp16x2 pair-permuted
__device__ __align__(16) unsigned g_W2h[16 * H2 * 8];   // fp16x2 pair-permuted
__device__ __align__(16) unsigned g_W3h[8 * C_OUT * 8]; // fp16x2 pair-permuted

// ---------------- helpers ----------------
__device__ __forceinline__ unsigned h2u(__half2 h) { return *reinterpret_cast<unsigned*>(&h); }
__device__ __forceinline__ __half2 u2h(unsigned u) { return *reinterpret_cast<__half2*>(&u); }

// half2 gelu (tanh approx as v*sigmoid(2u)); saturates correctly at +-inf
__device__ __forceinline__ __half2 gelu_h2(__half2 v) {
    const __half2 one = __float2half2_rn(1.0f);
    const __half2 c1  = __float2half2_rn(0.044715f);
    const __half2 c2  = __float2half2_rn(2.3022085f);   // 2*0.7978845608*log2(e)
    __half2 v2 = __hmul2(v, v);
    __half2 w  = __hfma2(c1, v2, one);
    __half2 u  = __hmul2(__hmul2(c2, v), w);
    __half2 e  = h2exp2(u);
    __half2 r  = h2rcp(__hadd2(one, e));
    return __hfma2(__hneg2(v), r, v);   // v*(1 - 1/(1+2^u))
}

__device__ __forceinline__ int pairpos(int j) {
    return ((j & 3) << 1) | ((j >> 2) & 1);
}

__device__ __forceinline__ unsigned packh2(float lo, float hi) {
    unsigned r;
    asm("cvt.rn.f16x2.f32 %0, %1, %2;" : "=r"(r) : "f"(hi), "f"(lo));
    return r;
}

__device__ __forceinline__ void hmma(float* c, const unsigned* a, const unsigned* b) {
    asm volatile(
        "mma.sync.aligned.m16n8k16.row.col.f32.f16.f16.f32 "
        "{%0,%1,%2,%3},{%4,%5,%6,%7},{%8,%9},{%0,%1,%2,%3};\n"
        : "+f"(c[0]), "+f"(c[1]), "+f"(c[2]), "+f"(c[3])
        : "r"(a[0]), "r"(a[1]), "r"(a[2]), "r"(a[3]), "r"(b[0]), "r"(b[1]));
}

__device__ __forceinline__ void cp_async16(unsigned smem_addr, const void* gptr) {
    asm volatile("cp.async.cg.shared.global [%0], [%1], 16;\n"
                 :: "r"(smem_addr), "l"(gptr));
}
__device__ __forceinline__ void cp_commit() {
    asm volatile("cp.async.commit_group;\n");
}
template <int N>
__device__ __forceinline__ void cp_wait() {
    asm volatile("cp.async.wait_group %0;\n" :: "n"(N));
}

// ============ kernel 1: fused node features + layer-1 factorization ========
// 64 nodes / block, 512 threads. Phase 2 uses fp16 mma; tables written half2.
// Also grid-spreads the W2h/W3h permutation for the edge kernel.
#define SIN_S 132
#define RS 514
#define SOUT_S 132
#define NOFF_WT   8448
#define NOFF_INH  16640
#define NOFF_W1H  20752
#define NSM_WORDS 37136
#define NSM_BYTES (NSM_WORDS * 4)

__global__ void __launch_bounds__(512) node_fused(
    const float* __restrict__ x, const float* __restrict__ y,
    const float* __restrict__ fx,
    const float* __restrict__ peW, const float* __restrict__ peb,
    const float* __restrict__ Wq, const float* __restrict__ bq,
    const float* __restrict__ Wk, const float* __restrict__ bk,
    const float* __restrict__ liftW, const float* __restrict__ liftb,
    const float* __restrict__ W1, const float* __restrict__ b1,
    const float* __restrict__ W2, const float* __restrict__ W3,
    float* __restrict__ out, int N)
{
    extern __shared__ float ns[];
    float* s_in  = ns;
    float* s_wt  = ns + NOFF_WT;
    unsigned* s_outU = (unsigned*)ns;            // [64][SOUT_S] half2 words, alias
    unsigned* s_inH = (unsigned*)(ns + NOFF_INH);
    unsigned* w1h   = (unsigned*)(ns + NOFF_W1H);

    const int tid  = threadIdx.x;
    const int lane = tid & 31;
    const int w    = tid >> 5;        // 0..15
    const int q    = lane & 3;
    const int g    = lane >> 2;
    const int n0   = blockIdx.x * 64;

    // --- grid-spread weight permutation for the edge kernel ---
    {
        int gidx = blockIdx.x * 512 + tid;
        if (gidx < 16384) {            // W2h: 128 k-pairs x 128 n
            int kp = gidx >> 7, n = gidx & 127;
            g_W2h[(kp >> 3) * (H2 * 8) + n * 8 + pairpos(kp & 7)] =
                packh2(__ldg(&W2[(2*kp) * H2 + n]), __ldg(&W2[(2*kp + 1) * H2 + n]));
        }
        if (gidx < 4096) {             // W3h: 64 k-pairs x 64 n
            int kp = gidx >> 6, n = gidx & 63;
            g_W3h[(kp >> 3) * (C_OUT * 8) + n * 8 + pairpos(kp & 7)] =
                packh2(__ldg(&W3[(2*kp) * C_OUT + n]), __ldg(&W3[(2*kp + 1) * C_OUT + n]));
        }
    }

    // --- permute W1 directly into local smem w1h (fp16 pair layout) ---
    {
        #pragma unroll
        for (int it = 0; it < 4; it++) {
            int i = tid + it * 512;       // [0, 2048)
            int kp = i >> 5;              // 0..63
            int nb = (i & 31) * 8;        // 0..255 step 8
            #pragma unroll
            for (int j = 0; j < 8; j++) {
                int n = nb + j;
                w1h[(kp >> 3) * (H1 * 8) + n * 8 + pairpos(kp & 7)] =
                    packh2(__ldg(&W1[(2*kp) * H1 + n]), __ldg(&W1[(2*kp + 1) * H1 + n]));
            }
        }
    }

    // --- stage Wq|Wk|liftW into s_wt ---
    *(float4*)&s_wt[tid * 4]          = __ldg((const float4*)Wq + tid);
    *(float4*)&s_wt[2048 + tid * 4]   = __ldg((const float4*)Wk + tid);
    *(float4*)&s_wt[4096 + tid * 4]   = __ldg((const float4*)liftW + tid);
    *(float4*)&s_wt[6144 + tid * 4]   = __ldg((const float4*)liftW + 512 + tid);

    // --- stage fx into s_in cols 64..127 ---
    #pragma unroll
    for (int it = 0; it < 2; it++) {
        int idx4 = tid + it * 512;
        int node = idx4 >> 4, c4 = (idx4 & 15) * 4;
        int n = n0 + node;
        float4 v = make_float4(0.f, 0.f, 0.f, 0.f);
        if (n < N) v = __ldg((const float4*)(fx + (size_t)n * C_F + c4));
        *(float4*)&s_in[node * SIN_S + 64 + c4] = v;
    }

    const int nl = tid >> 3, part = tid & 7;
    const int n = n0 + nl;
    const bool valid = (n < N);

    // --- xe/ye (4 channels per thread) ---
    {
        float x0 = 0, x1 = 0, x2 = 0, y0 = 0, y1 = 0, y2 = 0;
        if (valid) {
            x0 = x[n*3+0]; x1 = x[n*3+1]; x2 = x[n*3+2];
            y0 = y[n*3+0]; y1 = y[n*3+1]; y2 = y[n*3+2];
        }
        #pragma unroll
        for (int ii = 0; ii < 4; ii++) {
            int i = part * 4 + ii;
            float w0 = __ldg(&peW[i]), w1 = __ldg(&peW[C_POS + i]), w2 = __ldg(&peW[2*C_POS + i]);
            float b = __ldg(&peb[i]);
            s_in[nl*SIN_S + i]      = fmaf(y0, w0, fmaf(y1, w1, fmaf(y2, w2, b)));
            s_in[nl*SIN_S + 32 + i] = fmaf(x0, w0, fmaf(x1, w1, fmaf(x2, w2, b)));
        }
    }
    __syncthreads();

    // --- Q, K, femb (8 outputs per thread, jb = part*8) ---
    float facc[8];
    {
        const int jb = part * 8;
        float qacc[8], kacc[8];
        #pragma unroll
        for (int jj = 0; jj < 8; jj++) {
            qacc[jj] = __ldg(&bq[jb + jj]);
            kacc[jj] = __ldg(&bk[jb + jj]);
            facc[jj] = __ldg(&liftb[jb + jj]);
        }
        #pragma unroll
        for (int i = 0; i < C_POS; i++) {
            float ye = s_in[nl*SIN_S + i];
            float xe = s_in[nl*SIN_S + 32 + i];
            #pragma unroll
            for (int j4 = 0; j4 < 2; j4++) {
                float4 wq = *(const float4*)&s_wt[i*64 + jb + 4*j4];
                float4 wk = *(const float4*)&s_wt[2048 + i*64 + jb + 4*j4];
                qacc[4*j4+0] = fmaf(ye, wq.x, qacc[4*j4+0]);
                qacc[4*j4+1] = fmaf(ye, wq.y, qacc[4*j4+1]);
                qacc[4*j4+2] = fmaf(ye, wq.z, qacc[4*j4+2]);
                qacc[4*j4+3] = fmaf(ye, wq.w, qacc[4*j4+3]);
                kacc[4*j4+0] = fmaf(xe, wk.x, kacc[4*j4+0]);
                kacc[4*j4+1] = fmaf(xe, wk.y, kacc[4*j4+1]);
                kacc[4*j4+2] = fmaf(xe, wk.z, kacc[4*j4+2]);
                kacc[4*j4+3] = fmaf(xe, wk.w, kacc[4*j4+3]);
            }
        }
        #pragma unroll 8
        for (int k = 0; k < C_F; k++) {
            float f = s_in[nl*SIN_S + 64 + k];
            #pragma unroll
            for (int j4 = 0; j4 < 2; j4++) {
                float4 wl = *(const float4*)&s_wt[4096 + k*64 + jb + 4*j4];
                facc[4*j4+0] = fmaf(f, wl.x, facc[4*j4+0]);
                facc[4*j4+1] = fmaf(f, wl.y, facc[4*j4+1]);
                facc[4*j4+2] = fmaf(f, wl.z, facc[4*j4+2]);
                facc[4*j4+3] = fmaf(f, wl.w, facc[4*j4+3]);
            }
        }
        if (valid) {
            *(float4*)&g_Q[(size_t)n*C_OUT + jb]     = make_float4(qacc[0], qacc[1], qacc[2], qacc[3]);
            *(float4*)&g_Q[(size_t)n*C_OUT + jb + 4] = make_float4(qacc[4], qacc[5], qacc[6], qacc[7]);
            *(float4*)&g_K[(size_t)n*C_OUT + jb]     = make_float4(kacc[0], kacc[1], kacc[2], kacc[3]);
            *(float4*)&g_K[(size_t)n*C_OUT + jb + 4] = make_float4(kacc[4], kacc[5], kacc[6], kacc[7]);
            *(float4*)&g_femb[(size_t)n*C_OUT + jb]     = make_float4(facc[0], facc[1], facc[2], facc[3]);
            *(float4*)&g_femb[(size_t)n*C_OUT + jb + 4] = make_float4(facc[4], facc[5], facc[6], facc[7]);
        }
    }

    // --- init out rows / denom ---
    #pragma unroll
    for (int it = 0; it < 2; it++) {
        int idx4 = tid + it * 512;
        int nn = n0 + (idx4 >> 4);
        if (nn < N)
            *(float4*)&out[(size_t)nn * C_OUT + (idx4 & 15) * 4] =
                make_float4(0.f, 0.f, 0.f, 0.f);
    }
    if (tid < 64 && n0 + tid < N) g_denom[n0 + tid] = 0.0f;
    __syncthreads();   // all femb-loop reads of s_in done before overwrite

    // --- overwrite fx region with femb ---
    {
        const int jb = part * 8;
        *(float4*)&s_in[nl*SIN_S + 64 + jb]     = make_float4(facc[0], facc[1], facc[2], facc[3]);
        *(float4*)&s_in[nl*SIN_S + 64 + jb + 4] = make_float4(facc[4], facc[5], facc[6], facc[7]);
    }
    __syncthreads();

    // --- repack s_in [64x128] -> s_inH fp16 pair layout ---
    #pragma unroll
    for (int it = 0; it < 2; it++) {
        int row = it*32 + w*2 + (lane >> 4);
        int li = lane & 15;
        const float* src = &s_in[row*SIN_S + li*8];
        float4 a0 = *(const float4*)src;
        float4 a1 = *(const float4*)(src + 4);
        unsigned base = (li >> 1) * RS + row * 8 + (li & 1);
        s_inH[base + 0] = packh2(a0.x, a0.y);
        s_inH[base + 2] = packh2(a0.z, a0.w);
        s_inH[base + 4] = packh2(a1.x, a1.y);
        s_inH[base + 6] = packh2(a1.z, a1.w);
    }
    __syncthreads();

    // --- phase 2: in[64x128] @ W1[128x256] via fp16 mma ---
    const int wm = w & 1;
    const int wn = w >> 1;
    float cA[2][4][4], cB[2][4][4];
    #pragma unroll
    for (int mt = 0; mt < 2; mt++)
        #pragma unroll
        for (int nt = 0; nt < 4; nt++)
            #pragma unroll
            for (int i = 0; i < 4; i++) { cA[mt][nt][i] = 0.0f; cB[mt][nt][i] = 0.0f; }

    #pragma unroll
    for (int kg = 0; kg < 8; kg++) {
        unsigned a[2][4];
        #pragma unroll
        for (int mt = 0; mt < 2; mt++) {
            int row = wm*32 + mt*16 + g;
            uint2 lo = *(const uint2*)&s_inH[kg*RS + row*8 + 2*q];
            uint2 hi = *(const uint2*)&s_inH[kg*RS + (row+8)*8 + 2*q];
            a[mt][0] = lo.x; a[mt][1] = hi.x; a[mt][2] = lo.y; a[mt][3] = hi.y;
        }
        unsigned b[4][2];
        #pragma unroll
        for (int nt = 0; nt < 4; nt++) {
            int nn = wn*32 + nt*8 + g;
            uint2 bb = *(const uint2*)&w1h[kg*(H1*8) + nn*8 + 2*q];
            b[nt][0] = bb.x; b[nt][1] = bb.y;
        }
        if (kg < 2) {      // pass A: k 0..31 -> Ya
            #pragma unroll
            for (int mt = 0; mt < 2; mt++)
                #pragma unroll
                for (int nt = 0; nt < 4; nt++)
                    hmma(cA[mt][nt], a[mt], b[nt]);
        } else {           // pass B: k 32..127 -> XFc
            #pragma unroll
            for (int mt = 0; mt < 2; mt++)
                #pragma unroll
                for (int nt = 0; nt < 4; nt++)
                    hmma(cB[mt][nt], a[mt], b[nt]);
        }
    }
    __syncthreads();   // s_inH reads done; s_outU alias region free

    // --- epilogue A: Ya (half2 packed) -> s_outU -> g_YaH ---
    #pragma unroll
    for (int mt = 0; mt < 2; mt++) {
        #pragma unroll
        for (int nt = 0; nt < 4; nt++) {
            int cw = wn*16 + nt*4 + q;
            int r0 = wm*32 + mt*16 + g;
            s_outU[r0*SOUT_S + cw]     = packh2(cA[mt][nt][0], cA[mt][nt][1]);
            s_outU[(r0+8)*SOUT_S + cw] = packh2(cA[mt][nt][2], cA[mt][nt][3]);
        }
    }
    __syncthreads();
    #pragma unroll
    for (int it = 0; it < 4; it++) {
        int idx4 = tid + it * 512;
        int row = idx4 >> 5, c = idx4 & 31;
        uint4 v = *(const uint4*)&s_outU[row*SOUT_S + c*4];
        int nn = n0 + row;
        if (nn < N) ((uint4*)g_YaH)[(size_t)nn*32 + c] = v;
    }
    __syncthreads();

    // --- epilogue B: XFc + b1 (half2 packed) -> s_outU -> g_XFcH ---
    #pragma unroll
    for (int mt = 0; mt < 2; mt++) {
        #pragma unroll
        for (int nt = 0; nt < 4; nt++) {
            int cw = wn*16 + nt*4 + q;
            int col0 = 2*cw;
            int r0 = wm*32 + mt*16 + g;
            float bb0 = __ldg(&b1[col0]);
            float bb1 = __ldg(&b1[col0 + 1]);
            s_outU[r0*SOUT_S + cw]     = packh2(cB[mt][nt][0] + bb0, cB[mt][nt][1] + bb1);
            s_outU[(r0+8)*SOUT_S + cw] = packh2(cB[mt][nt][2] + bb0, cB[mt][nt][3] + bb1);
        }
    }
    __syncthreads();
    #pragma unroll
    for (int it = 0; it < 4; it++) {
        int idx4 = tid + it * 512;
        int row = idx4 >> 5, c = idx4 & 31;
        uint4 v = *(const uint4*)&s_outU[row*SOUT_S + c*4];
        int nn = n0 + row;
        if (nn < N) ((uint4*)g_XFcH)[(size_t)nn*32 + c] = v;
    }
}

// ---------------- kernel 2: scores + exp + warp-aggregated segment sum ------
__global__ void zscore_kernel(const int* __restrict__ src, const int* __restrict__ trg, int E) {
    int e = blockIdx.x * blockDim.x + threadIdx.x;
    const int lane = threadIdx.x & 31;
    bool valid = (e < E);
    int ec = valid ? e : (E - 1);
    int t = trg[ec], s = src[ec];

    const float4* q = (const float4*)(g_Q + (size_t)t * C_OUT);
    const float4* k = (const float4*)(g_K + (size_t)s * C_OUT);
    float sum = 0.0f;
    #pragma unroll
    for (int i = 0; i < C_OUT/4; i++) {
        float4 a = __ldg(&q[i]); float4 b = __ldg(&k[i]);
        sum = fmaf(a.x, b.x, sum);
        sum = fmaf(a.y, b.y, sum);
        sum = fmaf(a.z, b.z, sum);
        sum = fmaf(a.w, b.w, sum);
    }
    float z = valid ? __expf(sum * 0.125f) : 0.0f;
    if (valid) g_z[e] = z;

    // segmented suffix-sum over sorted t within the warp; run heads atomicAdd
    float acc = z;
    #pragma unroll
    for (int off = 1; off < 32; off <<= 1) {
        float v = __shfl_down_sync(0xFFFFFFFFu, acc, off);
        int  tv = __shfl_down_sync(0xFFFFFFFFu, t, off);
        if (lane + off < 32 && tv == t) acc += v;
    }
    int tprev = __shfl_up_sync(0xFFFFFFFFu, t, 1);
    if (lane == 0 || tprev != t) atomicAdd(&g_denom[t], acc);
}

// ---------------- kernel 3: edge MLP (round-10 pair layout) ----------------
#define OFF_H2H   4096
#define OFF_W2H   8224
#define OFF_W3H   24608
#define OFF_ALPHA 28704
#define OFF_TRG   28768
#define OFF_SRC   28832
#define ESM_WORDS 28896
#define ESM_BYTES (ESM_WORDS * 4)
#define NTHR2 512

__global__ void __launch_bounds__(NTHR2, 2) edge_kernel(
    const int* __restrict__ src, const int* __restrict__ trg,
    const float* __restrict__ b2, const float* __restrict__ b3,
    float* __restrict__ out, int E)
{
    extern __shared__ unsigned sm[];
    unsigned* h1h   = sm;
    unsigned* h2h   = sm + OFF_H2H;
    unsigned* w2h   = sm + OFF_W2H;
    unsigned* w3h   = sm + OFF_W3H;
    float*    s_alpha = (float*)(sm + OFF_ALPHA);
    int*      s_trg   = (int*)(sm + OFF_TRG);
    int*      s_src   = (int*)(sm + OFF_SRC);
    float*    s_out   = (float*)sm;   // [64][64], aliases h1h

    const int tid  = threadIdx.x;
    const int lane = tid & 31;
    const int w    = tid >> 5;
    const int q    = lane & 3;
    const int g    = lane >> 2;
    const int e0   = blockIdx.x * 64;

    // --- stage ALL weights via cp.async ---
    {
        unsigned w2base = __cvta_generic_to_shared(w2h);
        unsigned w3base = __cvta_generic_to_shared(w3h);
        #pragma unroll
        for (int i = 0; i < 8; i++) {
            int v4 = tid + i * NTHR2;
            cp_async16(w2base + v4 * 16, (const uint4*)g_W2h + v4);
        }
        #pragma unroll
        for (int i = 0; i < 2; i++) {
            int v4 = tid + i * NTHR2;
            cp_async16(w3base + v4 * 16, (const uint4*)g_W3h + v4);
        }
        cp_commit();
    }

    // --- metadata ---
    if (tid < 64) {
        int e = e0 + tid;
        int t, s; float al;
        if (e < E) { t = trg[e]; s = src[e]; al = g_z[e] / g_denom[t]; }
        else       { t = trg[E-1]; s = 0; al = 0.0f; }
        s_trg[tid] = t; s_src[tid] = s; s_alpha[tid] = al;
    }
    __syncthreads();

    // --- gather (half2 tables) + half2 gelu -> h1h (Ya dedup over runs) ---
    {
        int tprev = -1;
        uint4 ya4;
        #pragma unroll
        for (int rr = 0; rr < 4; rr++) {
            int row = w * 4 + rr;
            int t = s_trg[row], s = s_src[row];
            if (t != tprev) {
                ya4 = __ldg((const uint4*)g_YaH + (size_t)t * 32 + lane);
                tprev = t;
            }
            uint4 xf4 = __ldg((const uint4*)g_XFcH + (size_t)s * 32 + lane);
            __half2 p0 = gelu_h2(__hadd2(u2h(ya4.x), u2h(xf4.x)));
            __half2 p1 = gelu_h2(__hadd2(u2h(ya4.y), u2h(xf4.y)));
            __half2 p2 = gelu_h2(__hadd2(u2h(ya4.z), u2h(xf4.z)));
            __half2 p3 = gelu_h2(__hadd2(u2h(ya4.w), u2h(xf4.w)));
            unsigned base = (lane >> 1) * RS + row * 8 + (lane & 1);
            h1h[base + 0] = h2u(p0);
            h1h[base + 2] = h2u(p1);
            h1h[base + 4] = h2u(p2);
            h1h[base + 6] = h2u(p3);
        }
    }
    cp_wait<0>();
    __syncthreads();

    // --- layer 2 GEMM: h1[64x256] @ W2[256x128], fp16 mma ---
    const int wm = w & 1;
    const int wn = w >> 1;
    float c2[2][2][4];
    #pragma unroll
    for (int mt = 0; mt < 2; mt++)
        #pragma unroll
        for (int nt = 0; nt < 2; nt++)
            #pragma unroll
            for (int i = 0; i < 4; i++) c2[mt][nt][i] = 0.0f;

    #pragma unroll
    for (int kg = 0; kg < 16; kg++) {
        unsigned a[2][4];
        #pragma unroll
        for (int mt = 0; mt < 2; mt++) {
            int row = wm*32 + mt*16 + g;
            uint2 lo = *(const uint2*)&h1h[kg*RS + row*8 + 2*q];
            uint2 hi = *(const uint2*)&h1h[kg*RS + (row+8)*8 + 2*q];
            a[mt][0] = lo.x; a[mt][1] = hi.x; a[mt][2] = lo.y; a[mt][3] = hi.y;
        }
        unsigned b[2][2];
        #pragma unroll
        for (int nt = 0; nt < 2; nt++) {
            int n = wn*16 + nt*8 + g;
            uint2 bb = *(const uint2*)&w2h[kg*(H2*8) + n*8 + 2*q];
            b[nt][0] = bb.x; b[nt][1] = bb.y;
        }
        #pragma unroll
        for (int mt = 0; mt < 2; mt++)
            #pragma unroll
            for (int nt = 0; nt < 2; nt++)
                hmma(c2[mt][nt], a[mt], b[nt]);
    }
    __syncthreads();

    // --- layer 2 epilogue: bias + half2 gelu -> h2h ---
    #pragma unroll
    for (int mt = 0; mt < 2; mt++) {
        #pragma unroll
        for (int nt = 0; nt < 2; nt++) {
            int col0 = wn*16 + nt*8 + 2*q;
            int r0 = wm*32 + mt*16 + g;
            float bb0 = __ldg(&b2[col0]);
            float bb1 = __ldg(&b2[col0 + 1]);
            int kg2 = col0 >> 4;
            int pos = pairpos((col0 & 15) >> 1);
            __half2 lo = gelu_h2(u2h(packh2(c2[mt][nt][0] + bb0, c2[mt][nt][1] + bb1)));
            __half2 hi = gelu_h2(u2h(packh2(c2[mt][nt][2] + bb0, c2[mt][nt][3] + bb1)));
            h2h[kg2*RS + r0*8 + pos]     = h2u(lo);
            h2h[kg2*RS + (r0+8)*8 + pos] = h2u(hi);
        }
    }
    __syncthreads();

    // --- layer 3 GEMM: h2[64x128] @ W3[128x64], fp16 mma ---
    const int wm3 = w & 1;
    const int wn3 = w >> 1;
    float c3[2][4];
    #pragma unroll
    for (int mt = 0; mt < 2; mt++)
        #pragma unroll
        for (int i = 0; i < 4; i++) c3[mt][i] = 0.0f;

    #pragma unroll
    for (int kg = 0; kg < 8; kg++) {
        unsigned a[2][4];
        #pragma unroll
        for (int mt = 0; mt < 2; mt++) {
            int row = wm3*32 + mt*16 + g;
            uint2 lo = *(const uint2*)&h2h[kg*RS + row*8 + 2*q];
            uint2 hi = *(const uint2*)&h2h[kg*RS + (row+8)*8 + 2*q];
            a[mt][0] = lo.x; a[mt][1] = hi.x; a[mt][2] = lo.y; a[mt][3] = hi.y;
        }
        unsigned b[2];
        {
            int n = wn3*8 + g;
            uint2 bb = *(const uint2*)&w3h[kg*(C_OUT*8) + n*8 + 2*q];
            b[0] = bb.x; b[1] = bb.y;
        }
        hmma(c3[0], a[0], b);
        hmma(c3[1], a[1], b);
    }
    __syncthreads();

    // --- epilogue: alpha * (kout + b3) * f_src -> s_out ---
    {
        int col0 = wn3*8 + 2*q;
        float bb0 = __ldg(&b3[col0]);
        float bb1 = __ldg(&b3[col0 + 1]);
        #pragma unroll
        for (int mt = 0; mt < 2; mt++) {
            int r0 = wm3*32 + mt*16 + g;
            #pragma unroll
            for (int h = 0; h < 2; h++) {
                int row = r0 + h*8;
                float al = s_alpha[row];
                int s = s_src[row];
                float2 fs = __ldg((const float2*)(g_femb + (size_t)s * C_OUT + col0));
                float kv0 = c3[mt][h*2 + 0] + bb0;
                float kv1 = c3[mt][h*2 + 1] + bb1;
                *(float2*)&s_out[row*64 + col0] =
                    make_float2(al * kv0 * fs.x, al * kv1 * fs.y);
            }
        }
    }
    __syncthreads();

    // --- run reduction (trg sorted) + atomic scatter ---
    for (int idx = tid; idx < 2048; idx += NTHR2) {
        int r = idx >> 5, col = (idx & 31) * 2;
        int t = s_trg[r];
        if (r > 0 && s_trg[r-1] == t) continue;
        float sx = 0.0f, sy = 0.0f;
        for (int rr = r; rr < 64 && s_trg[rr] == t; rr++) {
            float2 v = *(const float2*)&s_out[rr*64 + col];
            sx += v.x; sy += v.y;
        }
        atomicAdd(&out[(size_t)t*C_OUT + col],     sx);
        atomicAdd(&out[(size_t)t*C_OUT + col + 1], sy);
    }
}

// ---------------- launch ----------------
extern "C" void kernel_launch(void* const* d_in, const int* in_sizes, int n_in,
                              void* d_out, int out_size)
{
    const float* x     = (const float*)d_in[0];
    const float* y     = (const float*)d_in[1];
    const float* fx    = (const float*)d_in[2];
    const int*   src   = (const int*)d_in[3];
    const int*   trg   = (const int*)d_in[4];
    const float* peW   = (const float*)d_in[5];
    const float* peb   = (const float*)d_in[6];
    const float* Wq    = (const float*)d_in[7];
    const float* bq    = (const float*)d_in[8];
    const float* Wk    = (const float*)d_in[9];
    const float* bk    = (const float*)d_in[10];
    const float* liftW = (const float*)d_in[11];
    const float* liftb = (const float*)d_in[12];
    const float* W1    = (const float*)d_in[13];
    const float* b1    = (const float*)d_in[14];
    const float* W2    = (const float*)d_in[15];
    const float* b2    = (const float*)d_in[16];
    const float* W3    = (const float*)d_in[17];
    const float* b3    = (const float*)d_in[18];

    int N = in_sizes[0] / 3;
    int E = in_sizes[3];
    float* out = (float*)d_out;

    cudaFuncSetAttribute(node_fused,
                         cudaFuncAttributeMaxDynamicSharedMemorySize, NSM_BYTES);
    node_fused<<<(N + 63)/64, 512, NSM_BYTES>>>(x, y, fx, peW, peb, Wq, bq, Wk, bk,
                                                liftW, liftb, W1, b1, W2, W3, out, N);
    zscore_kernel<<<(E + 255)/256, 256>>>(src, trg, E);

    cudaFuncSetAttribute(edge_kernel,
                         cudaFuncAttributeMaxDynamicSharedMemorySize, ESM_BYTES);
    edge_kernel<<<(E + 63)/64, NTHR2, ESM_BYTES>>>(src, trg, b2, b3, out, E);
}

// round 15
// speedup vs baseline: 1.0819x; 1.0819x over previous
#include <cuda_runtime.h>
#include <cuda_bf16.h>
#include <cuda_fp16.h>
#include <math.h>

// Problem constants
#define MAXN 20000
#define MAXE 480000
#define C_POS 32
#define C_OUT 64
#define C_F   64
#define H1    256
#define H2    128

// ---------------- scratch ----------------
__device__ float g_Q [MAXN * C_OUT];
__device__ float g_K [MAXN * C_OUT];
__device__ float g_femb[MAXN * C_OUT];
__device__ __align__(16) unsigned g_YaH [MAXN * 128];   // half2-packed Ya  [N][128]
__device__ __align__(16) unsigned g_XFcH[MAXN * 128];   // half2-packed XFc [N][128]
__device__ float g_z[MAXE];
__device__ float g_denom[MAXN];
__device__ __align__(16) unsigned g_W1h[8 * H1 * 8];    // fp16x2 pair-permuted
__device__ __align__(16) unsigned g_W2h[16 * H2 * 8];   // fp16x2 pair-permuted
__device__ __align__(16) unsigned g_W3h[8 * C_OUT * 8]; // fp16x2 pair-permuted

// ---------------- helpers ----------------
__device__ __forceinline__ unsigned h2u(__half2 h) { return *reinterpret_cast<unsigned*>(&h); }
__device__ __forceinline__ __half2 u2h(unsigned u) { return *reinterpret_cast<__half2*>(&u); }

// half2 gelu (tanh approx as v*sigmoid(2u)); saturates correctly at +-inf
__device__ __forceinline__ __half2 gelu_h2(__half2 v) {
    const __half2 one = __float2half2_rn(1.0f);
    const __half2 c1  = __float2half2_rn(0.044715f);
    const __half2 c2  = __float2half2_rn(2.3022085f);   // 2*0.7978845608*log2(e)
    __half2 v2 = __hmul2(v, v);
    __half2 w  = __hfma2(c1, v2, one);
    __half2 u  = __hmul2(__hmul2(c2, v), w);
    __half2 e  = h2exp2(u);
    __half2 r  = h2rcp(__hadd2(one, e));
    return __hfma2(__hneg2(v), r, v);   // v*(1 - 1/(1+2^u))
}

__device__ __forceinline__ int pairpos(int j) {
    return ((j & 3) << 1) | ((j >> 2) & 1);
}

__device__ __forceinline__ unsigned packh2(float lo, float hi) {
    unsigned r;
    asm("cvt.rn.f16x2.f32 %0, %1, %2;" : "=r"(r) : "f"(hi), "f"(lo));
    return r;
}

__device__ __forceinline__ void hmma(float* c, const unsigned* a, const unsigned* b) {
    asm volatile(
        "mma.sync.aligned.m16n8k16.row.col.f32.f16.f16.f32 "
        "{%0,%1,%2,%3},{%4,%5,%6,%7},{%8,%9},{%0,%1,%2,%3};\n"
        : "+f"(c[0]), "+f"(c[1]), "+f"(c[2]), "+f"(c[3])
        : "r"(a[0]), "r"(a[1]), "r"(a[2]), "r"(a[3]), "r"(b[0]), "r"(b[1]));
}

__device__ __forceinline__ void cp_async16(unsigned smem_addr, const void* gptr) {
    asm volatile("cp.async.cg.shared.global [%0], [%1], 16;\n"
                 :: "r"(smem_addr), "l"(gptr));
}
__device__ __forceinline__ void cp_commit() {
    asm volatile("cp.async.commit_group;\n");
}
template <int N>
__device__ __forceinline__ void cp_wait() {
    asm volatile("cp.async.wait_group %0;\n" :: "n"(N));
}

// ---------------- prep kernel: fp16 pair-permute W1/W2/W3 ----------------
__global__ void prep_kernel(const float* __restrict__ W1,
                            const float* __restrict__ W2,
                            const float* __restrict__ W3) {
    int i = blockIdx.x * blockDim.x + threadIdx.x;
    if (i < 16384) {                   // W1: 64 k-pairs x 256 n
        int kp = i >> 8, n = i & 255;
        g_W1h[(kp >> 3) * (H1 * 8) + n * 8 + pairpos(kp & 7)] =
            packh2(__ldg(&W1[(2*kp) * H1 + n]), __ldg(&W1[(2*kp + 1) * H1 + n]));
    }
    if (i < 16384) {                   // W2: 128 k-pairs x 128 n
        int kp = i >> 7, n = i & 127;
        g_W2h[(kp >> 3) * (H2 * 8) + n * 8 + pairpos(kp & 7)] =
            packh2(__ldg(&W2[(2*kp) * H2 + n]), __ldg(&W2[(2*kp + 1) * H2 + n]));
    }
    if (i < 4096) {                    // W3: 64 k-pairs x 64 n
        int kp = i >> 6, n = i & 63;
        g_W3h[(kp >> 3) * (C_OUT * 8) + n * 8 + pairpos(kp & 7)] =
            packh2(__ldg(&W3[(2*kp) * C_OUT + n]), __ldg(&W3[(2*kp + 1) * C_OUT + n]));
    }
}

// ============ kernel 2: fused node features + layer-1 factorization ========
// 64 nodes / block, 512 threads. Phase 2 uses fp16 mma; tables written half2.
#define SIN_S 132
#define RS 514
#define SOUT_S 132
#define NOFF_WT   8448
#define NOFF_INH  16640
#define NOFF_W1H  20752
#define NSM_WORDS 37136
#define NSM_BYTES (NSM_WORDS * 4)

__global__ void __launch_bounds__(512) node_fused(
    const float* __restrict__ x, const float* __restrict__ y,
    const float* __restrict__ fx,
    const float* __restrict__ peW, const float* __restrict__ peb,
    const float* __restrict__ Wq, const float* __restrict__ bq,
    const float* __restrict__ Wk, const float* __restrict__ bk,
    const float* __restrict__ liftW, const float* __restrict__ liftb,
    const float* __restrict__ b1,
    float* __restrict__ out, int N)
{
    extern __shared__ float ns[];
    float* s_in  = ns;
    float* s_wt  = ns + NOFF_WT;
    unsigned* s_outU = (unsigned*)ns;            // [64][SOUT_S] half2 words, alias
    unsigned* s_inH = (unsigned*)(ns + NOFF_INH);
    unsigned* w1h   = (unsigned*)(ns + NOFF_W1H);

    const int tid  = threadIdx.x;
    const int lane = tid & 31;
    const int w    = tid >> 5;        // 0..15
    const int q    = lane & 3;
    const int g    = lane >> 2;
    const int n0   = blockIdx.x * 64;

    // --- cp.async W1h (overlaps with all of phase 1) ---
    {
        unsigned w1base = __cvta_generic_to_shared(w1h);
        #pragma unroll
        for (int i = 0; i < 8; i++) {
            int v4 = tid + i * 512;
            cp_async16(w1base + v4 * 16, (const uint4*)g_W1h + v4);
        }
        cp_commit();
    }

    // --- stage Wq|Wk|liftW into s_wt ---
    *(float4*)&s_wt[tid * 4]          = __ldg((const float4*)Wq + tid);
    *(float4*)&s_wt[2048 + tid * 4]   = __ldg((const float4*)Wk + tid);
    *(float4*)&s_wt[4096 + tid * 4]   = __ldg((const float4*)liftW + tid);
    *(float4*)&s_wt[6144 + tid * 4]   = __ldg((const float4*)liftW + 512 + tid);

    // --- stage fx into s_in cols 64..127 ---
    #pragma unroll
    for (int it = 0; it < 2; it++) {
        int idx4 = tid + it * 512;
        int node = idx4 >> 4, c4 = (idx4 & 15) * 4;
        int n = n0 + node;
        float4 v = make_float4(0.f, 0.f, 0.f, 0.f);
        if (n < N) v = __ldg((const float4*)(fx + (size_t)n * C_F + c4));
        *(float4*)&s_in[node * SIN_S + 64 + c4] = v;
    }

    const int nl = tid >> 3, part = tid & 7;
    const int n = n0 + nl;
    const bool valid = (n < N);

    // --- xe/ye (4 channels per thread) ---
    {
        float x0 = 0, x1 = 0, x2 = 0, y0 = 0, y1 = 0, y2 = 0;
        if (valid) {
            x0 = x[n*3+0]; x1 = x[n*3+1]; x2 = x[n*3+2];
            y0 = y[n*3+0]; y1 = y[n*3+1]; y2 = y[n*3+2];
        }
        #pragma unroll
        for (int ii = 0; ii < 4; ii++) {
            int i = part * 4 + ii;
            float w0 = __ldg(&peW[i]), w1 = __ldg(&peW[C_POS + i]), w2 = __ldg(&peW[2*C_POS + i]);
            float b = __ldg(&peb[i]);
            s_in[nl*SIN_S + i]      = fmaf(y0, w0, fmaf(y1, w1, fmaf(y2, w2, b)));
            s_in[nl*SIN_S + 32 + i] = fmaf(x0, w0, fmaf(x1, w1, fmaf(x2, w2, b)));
        }
    }
    __syncthreads();

    // --- Q, K, femb (8 outputs per thread, jb = part*8) ---
    float facc[8];
    {
        const int jb = part * 8;
        float qacc[8], kacc[8];
        #pragma unroll
        for (int jj = 0; jj < 8; jj++) {
            qacc[jj] = __ldg(&bq[jb + jj]);
            kacc[jj] = __ldg(&bk[jb + jj]);
            facc[jj] = __ldg(&liftb[jb + jj]);
        }
        #pragma unroll
        for (int i = 0; i < C_POS; i++) {
            float ye = s_in[nl*SIN_S + i];
            float xe = s_in[nl*SIN_S + 32 + i];
            #pragma unroll
            for (int j4 = 0; j4 < 2; j4++) {
                float4 wq = *(const float4*)&s_wt[i*64 + jb + 4*j4];
                float4 wk = *(const float4*)&s_wt[2048 + i*64 + jb + 4*j4];
                qacc[4*j4+0] = fmaf(ye, wq.x, qacc[4*j4+0]);
                qacc[4*j4+1] = fmaf(ye, wq.y, qacc[4*j4+1]);
                qacc[4*j4+2] = fmaf(ye, wq.z, qacc[4*j4+2]);
                qacc[4*j4+3] = fmaf(ye, wq.w, qacc[4*j4+3]);
                kacc[4*j4+0] = fmaf(xe, wk.x, kacc[4*j4+0]);
                kacc[4*j4+1] = fmaf(xe, wk.y, kacc[4*j4+1]);
                kacc[4*j4+2] = fmaf(xe, wk.z, kacc[4*j4+2]);
                kacc[4*j4+3] = fmaf(xe, wk.w, kacc[4*j4+3]);
            }
        }
        #pragma unroll 8
        for (int k = 0; k < C_F; k++) {
            float f = s_in[nl*SIN_S + 64 + k];
            #pragma unroll
            for (int j4 = 0; j4 < 2; j4++) {
                float4 wl = *(const float4*)&s_wt[4096 + k*64 + jb + 4*j4];
                facc[4*j4+0] = fmaf(f, wl.x, facc[4*j4+0]);
                facc[4*j4+1] = fmaf(f, wl.y, facc[4*j4+1]);
                facc[4*j4+2] = fmaf(f, wl.z, facc[4*j4+2]);
                facc[4*j4+3] = fmaf(f, wl.w, facc[4*j4+3]);
            }
        }
        if (valid) {
            *(float4*)&g_Q[(size_t)n*C_OUT + jb]     = make_float4(qacc[0], qacc[1], qacc[2], qacc[3]);
            *(float4*)&g_Q[(size_t)n*C_OUT + jb + 4] = make_float4(qacc[4], qacc[5], qacc[6], qacc[7]);
            *(float4*)&g_K[(size_t)n*C_OUT + jb]     = make_float4(kacc[0], kacc[1], kacc[2], kacc[3]);
            *(float4*)&g_K[(size_t)n*C_OUT + jb + 4] = make_float4(kacc[4], kacc[5], kacc[6], kacc[7]);
            *(float4*)&g_femb[(size_t)n*C_OUT + jb]     = make_float4(facc[0], facc[1], facc[2], facc[3]);
            *(float4*)&g_femb[(size_t)n*C_OUT + jb + 4] = make_float4(facc[4], facc[5], facc[6], facc[7]);
        }
    }

    // --- init out rows / denom ---
    #pragma unroll
    for (int it = 0; it < 2; it++) {
        int idx4 = tid + it * 512;
        int nn = n0 + (idx4 >> 4);
        if (nn < N)
            *(float4*)&out[(size_t)nn * C_OUT + (idx4 & 15) * 4] =
                make_float4(0.f, 0.f, 0.f, 0.f);
    }
    if (tid < 64 && n0 + tid < N) g_denom[n0 + tid] = 0.0f;
    __syncthreads();   // all femb-loop reads of s_in done before overwrite

    // --- overwrite fx region with femb ---
    {
        const int jb = part * 8;
        *(float4*)&s_in[nl*SIN_S + 64 + jb]     = make_float4(facc[0], facc[1], facc[2], facc[3]);
        *(float4*)&s_in[nl*SIN_S + 64 + jb + 4] = make_float4(facc[4], facc[5], facc[6], facc[7]);
    }
    __syncthreads();

    // --- repack s_in [64x128] -> s_inH fp16 pair layout ---
    #pragma unroll
    for (int it = 0; it < 2; it++) {
        int row = it*32 + w*2 + (lane >> 4);
        int li = lane & 15;
        const float* src = &s_in[row*SIN_S + li*8];
        float4 a0 = *(const float4*)src;
        float4 a1 = *(const float4*)(src + 4);
        unsigned base = (li >> 1) * RS + row * 8 + (li & 1);
        s_inH[base + 0] = packh2(a0.x, a0.y);
        s_inH[base + 2] = packh2(a0.z, a0.w);
        s_inH[base + 4] = packh2(a1.x, a1.y);
        s_inH[base + 6] = packh2(a1.z, a1.w);
    }
    cp_wait<0>();
    __syncthreads();

    // --- phase 2: in[64x128] @ W1[128x256] via fp16 mma ---
    const int wm = w & 1;
    const int wn = w >> 1;
    float cA[2][4][4], cB[2][4][4];
    #pragma unroll
    for (int mt = 0; mt < 2; mt++)
        #pragma unroll
        for (int nt = 0; nt < 4; nt++)
            #pragma unroll
            for (int i = 0; i < 4; i++) { cA[mt][nt][i] = 0.0f; cB[mt][nt][i] = 0.0f; }

    #pragma unroll
    for (int kg = 0; kg < 8; kg++) {
        unsigned a[2][4];
        #pragma unroll
        for (int mt = 0; mt < 2; mt++) {
            int row = wm*32 + mt*16 + g;
            uint2 lo = *(const uint2*)&s_inH[kg*RS + row*8 + 2*q];
            uint2 hi = *(const uint2*)&s_inH[kg*RS + (row+8)*8 + 2*q];
            a[mt][0] = lo.x; a[mt][1] = hi.x; a[mt][2] = lo.y; a[mt][3] = hi.y;
        }
        unsigned b[4][2];
        #pragma unroll
        for (int nt = 0; nt < 4; nt++) {
            int nn = wn*32 + nt*8 + g;
            uint2 bb = *(const uint2*)&w1h[kg*(H1*8) + nn*8 + 2*q];
            b[nt][0] = bb.x; b[nt][1] = bb.y;
        }
        if (kg < 2) {      // pass A: k 0..31 -> Ya
            #pragma unroll
            for (int mt = 0; mt < 2; mt++)
                #pragma unroll
                for (int nt = 0; nt < 4; nt++)
                    hmma(cA[mt][nt], a[mt], b[nt]);
        } else {           // pass B: k 32..127 -> XFc
            #pragma unroll
            for (int mt = 0; mt < 2; mt++)
                #pragma unroll
                for (int nt = 0; nt < 4; nt++)
                    hmma(cB[mt][nt], a[mt], b[nt]);
        }
    }
    __syncthreads();   // s_inH reads done; s_outU alias region free

    // --- epilogue A: Ya (half2 packed) -> s_outU -> g_YaH ---
    #pragma unroll
    for (int mt = 0; mt < 2; mt++) {
        #pragma unroll
        for (int nt = 0; nt < 4; nt++) {
            int cw = wn*16 + nt*4 + q;
            int r0 = wm*32 + mt*16 + g;
            s_outU[r0*SOUT_S + cw]     = packh2(cA[mt][nt][0], cA[mt][nt][1]);
            s_outU[(r0+8)*SOUT_S + cw] = packh2(cA[mt][nt][2], cA[mt][nt][3]);
        }
    }
    __syncthreads();
    #pragma unroll
    for (int it = 0; it < 4; it++) {
        int idx4 = tid + it * 512;
        int row = idx4 >> 5, c = idx4 & 31;
        uint4 v = *(const uint4*)&s_outU[row*SOUT_S + c*4];
        int nn = n0 + row;
        if (nn < N) ((uint4*)g_YaH)[(size_t)nn*32 + c] = v;
    }
    __syncthreads();

    // --- epilogue B: XFc + b1 (half2 packed) -> s_outU -> g_XFcH ---
    #pragma unroll
    for (int mt = 0; mt < 2; mt++) {
        #pragma unroll
        for (int nt = 0; nt < 4; nt++) {
            int cw = wn*16 + nt*4 + q;
            int col0 = 2*cw;
            int r0 = wm*32 + mt*16 + g;
            float bb0 = __ldg(&b1[col0]);
            float bb1 = __ldg(&b1[col0 + 1]);
            s_outU[r0*SOUT_S + cw]     = packh2(cB[mt][nt][0] + bb0, cB[mt][nt][1] + bb1);
            s_outU[(r0+8)*SOUT_S + cw] = packh2(cB[mt][nt][2] + bb0, cB[mt][nt][3] + bb1);
        }
    }
    __syncthreads();
    #pragma unroll
    for (int it = 0; it < 4; it++) {
        int idx4 = tid + it * 512;
        int row = idx4 >> 5, c = idx4 & 31;
        uint4 v = *(const uint4*)&s_outU[row*SOUT_S + c*4];
        int nn = n0 + row;
        if (nn < N) ((uint4*)g_XFcH)[(size_t)nn*32 + c] = v;
    }
}

// ---------------- kernel 3: scores + exp + warp-aggregated segment sum ------
__global__ void zscore_kernel(const int* __restrict__ src, const int* __restrict__ trg, int E) {
    int e = blockIdx.x * blockDim.x + threadIdx.x;
    const int lane = threadIdx.x & 31;
    bool valid = (e < E);
    int ec = valid ? e : (E - 1);
    int t = trg[ec], s = src[ec];

    const float4* q = (const float4*)(g_Q + (size_t)t * C_OUT);
    const float4* k = (const float4*)(g_K + (size_t)s * C_OUT);
    float sum = 0.0f;
    #pragma unroll
    for (int i = 0; i < C_OUT/4; i++) {
        float4 a = __ldg(&q[i]); float4 b = __ldg(&k[i]);
        sum = fmaf(a.x, b.x, sum);
        sum = fmaf(a.y, b.y, sum);
        sum = fmaf(a.z, b.z, sum);
        sum = fmaf(a.w, b.w, sum);
    }
    float z = valid ? __expf(sum * 0.125f) : 0.0f;
    if (valid) g_z[e] = z;

    // segmented suffix-sum over sorted t within the warp; run heads atomicAdd
    float acc = z;
    #pragma unroll
    for (int off = 1; off < 32; off <<= 1) {
        float v = __shfl_down_sync(0xFFFFFFFFu, acc, off);
        int  tv = __shfl_down_sync(0xFFFFFFFFu, t, off);
        if (lane + off < 32 && tv == t) acc += v;
    }
    int tprev = __shfl_up_sync(0xFFFFFFFFu, t, 1);
    if (lane == 0 || tprev != t) atomicAdd(&g_denom[t], acc);
}

// ---------------- kernel 4: edge MLP (round-10 pair layout) ----------------
#define OFF_H2H   4096
#define OFF_W2H   8224
#define OFF_W3H   24608
#define OFF_ALPHA 28704
#define OFF_TRG   28768
#define OFF_SRC   28832
#define ESM_WORDS 28896
#define ESM_BYTES (ESM_WORDS * 4)
#define NTHR2 512

__global__ void __launch_bounds__(NTHR2, 2) edge_kernel(
    const int* __restrict__ src, const int* __restrict__ trg,
    const float* __restrict__ b2, const float* __restrict__ b3,
    float* __restrict__ out, int E)
{
    extern __shared__ unsigned sm[];
    unsigned* h1h   = sm;
    unsigned* h2h   = sm + OFF_H2H;
    unsigned* w2h   = sm + OFF_W2H;
    unsigned* w3h   = sm + OFF_W3H;
    float*    s_alpha = (float*)(sm + OFF_ALPHA);
    int*      s_trg   = (int*)(sm + OFF_TRG);
    int*      s_src   = (int*)(sm + OFF_SRC);
    float*    s_out   = (float*)sm;   // [64][64], aliases h1h

    const int tid  = threadIdx.x;
    const int lane = tid & 31;
    const int w    = tid >> 5;
    const int q    = lane & 3;
    const int g    = lane >> 2;
    const int e0   = blockIdx.x * 64;

    // --- stage ALL weights via cp.async ---
    {
        unsigned w2base = __cvta_generic_to_shared(w2h);
        unsigned w3base = __cvta_generic_to_shared(w3h);
        #pragma unroll
        for (int i = 0; i < 8; i++) {
            int v4 = tid + i * NTHR2;
            cp_async16(w2base + v4 * 16, (const uint4*)g_W2h + v4);
        }
        #pragma unroll
        for (int i = 0; i < 2; i++) {
            int v4 = tid + i * NTHR2;
            cp_async16(w3base + v4 * 16, (const uint4*)g_W3h + v4);
        }
        cp_commit();
    }

    // --- metadata ---
    if (tid < 64) {
        int e = e0 + tid;
        int t, s; float al;
        if (e < E) { t = trg[e]; s = src[e]; al = g_z[e] / g_denom[t]; }
        else       { t = trg[E-1]; s = 0; al = 0.0f; }
        s_trg[tid] = t; s_src[tid] = s; s_alpha[tid] = al;
    }
    __syncthreads();

    // --- gather (half2 tables) + half2 gelu -> h1h (Ya dedup over runs) ---
    {
        int tprev = -1;
        uint4 ya4;
        #pragma unroll
        for (int rr = 0; rr < 4; rr++) {
            int row = w * 4 + rr;
            int t = s_trg[row], s = s_src[row];
            if (t != tprev) {
                ya4 = __ldg((const uint4*)g_YaH + (size_t)t * 32 + lane);
                tprev = t;
            }
            uint4 xf4 = __ldg((const uint4*)g_XFcH + (size_t)s * 32 + lane);
            __half2 p0 = gelu_h2(__hadd2(u2h(ya4.x), u2h(xf4.x)));
            __half2 p1 = gelu_h2(__hadd2(u2h(ya4.y), u2h(xf4.y)));
            __half2 p2 = gelu_h2(__hadd2(u2h(ya4.z), u2h(xf4.z)));
            __half2 p3 = gelu_h2(__hadd2(u2h(ya4.w), u2h(xf4.w)));
            unsigned base = (lane >> 1) * RS + row * 8 + (lane & 1);
            h1h[base + 0] = h2u(p0);
            h1h[base + 2] = h2u(p1);
            h1h[base + 4] = h2u(p2);
            h1h[base + 6] = h2u(p3);
        }
    }
    cp_wait<0>();
    __syncthreads();

    // --- layer 2 GEMM: h1[64x256] @ W2[256x128], fp16 mma ---
    const int wm = w & 1;
    const int wn = w >> 1;
    float c2[2][2][4];
    #pragma unroll
    for (int mt = 0; mt < 2; mt++)
        #pragma unroll
        for (int nt = 0; nt < 2; nt++)
            #pragma unroll
            for (int i = 0; i < 4; i++) c2[mt][nt][i] = 0.0f;

    #pragma unroll
    for (int kg = 0; kg < 16; kg++) {
        unsigned a[2][4];
        #pragma unroll
        for (int mt = 0; mt < 2; mt++) {
            int row = wm*32 + mt*16 + g;
            uint2 lo = *(const uint2*)&h1h[kg*RS + row*8 + 2*q];
            uint2 hi = *(const uint2*)&h1h[kg*RS + (row+8)*8 + 2*q];
            a[mt][0] = lo.x; a[mt][1] = hi.x; a[mt][2] = lo.y; a[mt][3] = hi.y;
        }
        unsigned b[2][2];
        #pragma unroll
        for (int nt = 0; nt < 2; nt++) {
            int n = wn*16 + nt*8 + g;
            uint2 bb = *(const uint2*)&w2h[kg*(H2*8) + n*8 + 2*q];
            b[nt][0] = bb.x; b[nt][1] = bb.y;
        }
        #pragma unroll
        for (int mt = 0; mt < 2; mt++)
            #pragma unroll
            for (int nt = 0; nt < 2; nt++)
                hmma(c2[mt][nt], a[mt], b[nt]);
    }
    __syncthreads();

    // --- layer 2 epilogue: bias + half2 gelu -> h2h ---
    #pragma unroll
    for (int mt = 0; mt < 2; mt++) {
        #pragma unroll
        for (int nt = 0; nt < 2; nt++) {
            int col0 = wn*16 + nt*8 + 2*q;
            int r0 = wm*32 + mt*16 + g;
            float bb0 = __ldg(&b2[col0]);
            float bb1 = __ldg(&b2[col0 + 1]);
            int kg2 = col0 >> 4;
            int pos = pairpos((col0 & 15) >> 1);
            __half2 lo = gelu_h2(u2h(packh2(c2[mt][nt][0] + bb0, c2[mt][nt][1] + bb1)));
            __half2 hi = gelu_h2(u2h(packh2(c2[mt][nt][2] + bb0, c2[mt][nt][3] + bb1)));
            h2h[kg2*RS + r0*8 + pos]     = h2u(lo);
            h2h[kg2*RS + (r0+8)*8 + pos] = h2u(hi);
        }
    }
    __syncthreads();

    // --- layer 3 GEMM: h2[64x128] @ W3[128x64], fp16 mma ---
    const int wm3 = w & 1;
    const int wn3 = w >> 1;
    float c3[2][4];
    #pragma unroll
    for (int mt = 0; mt < 2; mt++)
        #pragma unroll
        for (int i = 0; i < 4; i++) c3[mt][i] = 0.0f;

    #pragma unroll
    for (int kg = 0; kg < 8; kg++) {
        unsigned a[2][4];
        #pragma unroll
        for (int mt = 0; mt < 2; mt++) {
            int row = wm3*32 + mt*16 + g;
            uint2 lo = *(const uint2*)&h2h[kg*RS + row*8 + 2*q];
            uint2 hi = *(const uint2*)&h2h[kg*RS + (row+8)*8 + 2*q];
            a[mt][0] = lo.x; a[mt][1] = hi.x; a[mt][2] = lo.y; a[mt][3] = hi.y;
        }
        unsigned b[2];
        {
            int n = wn3*8 + g;
            uint2 bb = *(const uint2*)&w3h[kg*(C_OUT*8) + n*8 + 2*q];
            b[0] = bb.x; b[1] = bb.y;
        }
        hmma(c3[0], a[0], b);
        hmma(c3[1], a[1], b);
    }
    __syncthreads();

    // --- epilogue: alpha * (kout + b3) * f_src -> s_out ---
    {
        int col0 = wn3*8 + 2*q;
        float bb0 = __ldg(&b3[col0]);
        float bb1 = __ldg(&b3[col0 + 1]);
        #pragma unroll
        for (int mt = 0; mt < 2; mt++) {
            int r0 = wm3*32 + mt*16 + g;
            #pragma unroll
            for (int h = 0; h < 2; h++) {
                int row = r0 + h*8;
                float al = s_alpha[row];
                int s = s_src[row];
                float2 fs = __ldg((const float2*)(g_femb + (size_t)s * C_OUT + col0));
                float kv0 = c3[mt][h*2 + 0] + bb0;
                float kv1 = c3[mt][h*2 + 1] + bb1;
                *(float2*)&s_out[row*64 + col0] =
                    make_float2(al * kv0 * fs.x, al * kv1 * fs.y);
            }
        }
    }
    __syncthreads();

    // --- run reduction (trg sorted) + atomic scatter ---
    for (int idx = tid; idx < 2048; idx += NTHR2) {
        int r = idx >> 5, col = (idx & 31) * 2;
        int t = s_trg[r];
        if (r > 0 && s_trg[r-1] == t) continue;
        float sx = 0.0f, sy = 0.0f;
        for (int rr = r; rr < 64 && s_trg[rr] == t; rr++) {
            float2 v = *(const float2*)&s_out[rr*64 + col];
            sx += v.x; sy += v.y;
        }
        atomicAdd(&out[(size_t)t*C_OUT + col],     sx);
        atomicAdd(&out[(size_t)t*C_OUT + col + 1], sy);
    }
}

// ---------------- launch ----------------
extern "C" void kernel_launch(void* const* d_in, const int* in_sizes, int n_in,
                              void* d_out, int out_size)
{
    const float* x     = (const float*)d_in[0];
    const float* y     = (const float*)d_in[1];
    const float* fx    = (const float*)d_in[2];
    const int*   src   = (const int*)d_in[3];
    const int*   trg   = (const int*)d_in[4];
    const float* peW   = (const float*)d_in[5];
    const float* peb   = (const float*)d_in[6];
    const float* Wq    = (const float*)d_in[7];
    const float* bq    = (const float*)d_in[8];
    const float* Wk    = (const float*)d_in[9];
    const float* bk    = (const float*)d_in[10];
    const float* liftW = (const float*)d_in[11];
    const float* liftb = (const float*)d_in[12];
    const float* W1    = (const float*)d_in[13];
    const float* b1    = (const float*)d_in[14];
    const float* W2    = (const float*)d_in[15];
    const float* b2    = (const float*)d_in[16];
    const float* W3    = (const float*)d_in[17];
    const float* b3    = (const float*)d_in[18];

    int N = in_sizes[0] / 3;
    int E = in_sizes[3];
    float* out = (float*)d_out;

    prep_kernel<<<64, 256>>>(W1, W2, W3);

    cudaFuncSetAttribute(node_fused,
                         cudaFuncAttributeMaxDynamicSharedMemorySize, NSM_BYTES);
    node_fused<<<(N + 63)/64, 512, NSM_BYTES>>>(x, y, fx, peW, peb, Wq, bq, Wk, bk,
                                                liftW, liftb, b1, out, N);
    zscore_kernel<<<(E + 255)/256, 256>>>(src, trg, E);

    cudaFuncSetAttribute(edge_kernel,
                         cudaFuncAttributeMaxDynamicSharedMemorySize, ESM_BYTES);
    edge_kernel<<<(E + 63)/64, NTHR2, ESM_BYTES>>>(src, trg, b2, b3, out, E);
}

// round 16
// speedup vs baseline: 1.0919x; 1.0092x over previous
#include <cuda_runtime.h>
#include <cuda_bf16.h>
#include <cuda_fp16.h>
#include <math.h>

// Problem constants
#define MAXN 20000
#define MAXE 480000
#define C_POS 32
#define C_OUT 64
#define C_F   64
#define H1    256
#define H2    128

// ---------------- scratch ----------------
__device__ float g_Q [MAXN * C_OUT];
__device__ float g_K [MAXN * C_OUT];
__device__ float g_femb[MAXN * C_OUT];
__device__ __align__(16) unsigned g_YaH [MAXN * 128];   // half2-packed Ya  [N][128]
__device__ __align__(16) unsigned g_XFcH[MAXN * 128];   // half2-packed XFc [N][128]
__device__ float g_z[MAXE];
__device__ float g_denom[MAXN];
__device__ __align__(16) unsigned g_W1h[8 * H1 * 8];    // fp16x2 pair-permuted
__device__ __align__(16) unsigned g_W2h[16 * H2 * 8];   // fp16x2 pair-permuted
__device__ __align__(16) unsigned g_W3h[8 * C_OUT * 8]; // fp16x2 pair-permuted

// ---------------- helpers ----------------
__device__ __forceinline__ unsigned h2u(__half2 h) { return *reinterpret_cast<unsigned*>(&h); }
__device__ __forceinline__ __half2 u2h(unsigned u) { return *reinterpret_cast<__half2*>(&u); }

// half2 gelu (tanh approx as v*sigmoid(2u)); saturates correctly at +-inf
__device__ __forceinline__ __half2 gelu_h2(__half2 v) {
    const __half2 one = __float2half2_rn(1.0f);
    const __half2 c1  = __float2half2_rn(0.044715f);
    const __half2 c2  = __float2half2_rn(2.3022085f);   // 2*0.7978845608*log2(e)
    __half2 v2 = __hmul2(v, v);
    __half2 w  = __hfma2(c1, v2, one);
    __half2 u  = __hmul2(__hmul2(c2, v), w);
    __half2 e  = h2exp2(u);
    __half2 r  = h2rcp(__hadd2(one, e));
    return __hfma2(__hneg2(v), r, v);   // v*(1 - 1/(1+2^u))
}

__device__ __forceinline__ int pairpos(int j) {
    return ((j & 3) << 1) | ((j >> 2) & 1);
}

__device__ __forceinline__ unsigned packh2(float lo, float hi) {
    unsigned r;
    asm("cvt.rn.f16x2.f32 %0, %1, %2;" : "=r"(r) : "f"(hi), "f"(lo));
    return r;
}

__device__ __forceinline__ void hmma(float* c, const unsigned* a, const unsigned* b) {
    asm volatile(
        "mma.sync.aligned.m16n8k16.row.col.f32.f16.f16.f32 "
        "{%0,%1,%2,%3},{%4,%5,%6,%7},{%8,%9},{%0,%1,%2,%3};\n"
        : "+f"(c[0]), "+f"(c[1]), "+f"(c[2]), "+f"(c[3])
        : "r"(a[0]), "r"(a[1]), "r"(a[2]), "r"(a[3]), "r"(b[0]), "r"(b[1]));
}

__device__ __forceinline__ void cp_async16(unsigned smem_addr, const void* gptr) {
    asm volatile("cp.async.cg.shared.global [%0], [%1], 16;\n"
                 :: "r"(smem_addr), "l"(gptr));
}
__device__ __forceinline__ void cp_commit() {
    asm volatile("cp.async.commit_group;\n");
}
template <int N>
__device__ __forceinline__ void cp_wait() {
    asm volatile("cp.async.wait_group %0;\n" :: "n"(N));
}

// ---------------- prep kernel: fp16 pair-permute W1/W2/W3 ----------------
__global__ void prep_kernel(const float* __restrict__ W1,
                            const float* __restrict__ W2,
                            const float* __restrict__ W3) {
    int i = blockIdx.x * blockDim.x + threadIdx.x;
    if (i < 16384) {                   // W1: 64 k-pairs x 256 n
        int kp = i >> 8, n = i & 255;
        g_W1h[(kp >> 3) * (H1 * 8) + n * 8 + pairpos(kp & 7)] =
            packh2(__ldg(&W1[(2*kp) * H1 + n]), __ldg(&W1[(2*kp + 1) * H1 + n]));
    }
    if (i < 16384) {                   // W2: 128 k-pairs x 128 n
        int kp = i >> 7, n = i & 127;
        g_W2h[(kp >> 3) * (H2 * 8) + n * 8 + pairpos(kp & 7)] =
            packh2(__ldg(&W2[(2*kp) * H2 + n]), __ldg(&W2[(2*kp + 1) * H2 + n]));
    }
    if (i < 4096) {                    // W3: 64 k-pairs x 64 n
        int kp = i >> 6, n = i & 63;
        g_W3h[(kp >> 3) * (C_OUT * 8) + n * 8 + pairpos(kp & 7)] =
            packh2(__ldg(&W3[(2*kp) * C_OUT + n]), __ldg(&W3[(2*kp + 1) * C_OUT + n]));
    }
}

// ============ kernel 2: fused node features + layer-1 factorization ========
// 64 nodes / block, 512 threads. Phase 2 uses fp16 mma; tables written half2.
#define SIN_S 132
#define RS 514
#define SOUT_S 132
#define NOFF_WT   8448
#define NOFF_INH  16640
#define NOFF_W1H  20752
#define NSM_WORDS 37136
#define NSM_BYTES (NSM_WORDS * 4)

__global__ void __launch_bounds__(512) node_fused(
    const float* __restrict__ x, const float* __restrict__ y,
    const float* __restrict__ fx,
    const float* __restrict__ peW, const float* __restrict__ peb,
    const float* __restrict__ Wq, const float* __restrict__ bq,
    const float* __restrict__ Wk, const float* __restrict__ bk,
    const float* __restrict__ liftW, const float* __restrict__ liftb,
    const float* __restrict__ b1,
    float* __restrict__ out, int N)
{
    extern __shared__ float ns[];
    float* s_in  = ns;
    float* s_wt  = ns + NOFF_WT;
    unsigned* s_outU = (unsigned*)ns;            // [64][SOUT_S] half2 words, alias
    unsigned* s_inH = (unsigned*)(ns + NOFF_INH);
    unsigned* w1h   = (unsigned*)(ns + NOFF_W1H);

    const int tid  = threadIdx.x;
    const int lane = tid & 31;
    const int w    = tid >> 5;        // 0..15
    const int q    = lane & 3;
    const int g    = lane >> 2;
    const int n0   = blockIdx.x * 64;

    // --- cp.async W1h (overlaps with all of phase 1) ---
    {
        unsigned w1base = __cvta_generic_to_shared(w1h);
        #pragma unroll
        for (int i = 0; i < 8; i++) {
            int v4 = tid + i * 512;
            cp_async16(w1base + v4 * 16, (const uint4*)g_W1h + v4);
        }
        cp_commit();
    }

    // --- stage Wq|Wk|liftW into s_wt ---
    *(float4*)&s_wt[tid * 4]          = __ldg((const float4*)Wq + tid);
    *(float4*)&s_wt[2048 + tid * 4]   = __ldg((const float4*)Wk + tid);
    *(float4*)&s_wt[4096 + tid * 4]   = __ldg((const float4*)liftW + tid);
    *(float4*)&s_wt[6144 + tid * 4]   = __ldg((const float4*)liftW + 512 + tid);

    // --- stage fx into s_in cols 64..127 ---
    #pragma unroll
    for (int it = 0; it < 2; it++) {
        int idx4 = tid + it * 512;
        int node = idx4 >> 4, c4 = (idx4 & 15) * 4;
        int n = n0 + node;
        float4 v = make_float4(0.f, 0.f, 0.f, 0.f);
        if (n < N) v = __ldg((const float4*)(fx + (size_t)n * C_F + c4));
        *(float4*)&s_in[node * SIN_S + 64 + c4] = v;
    }

    const int nl = tid >> 3, part = tid & 7;
    const int n = n0 + nl;
    const bool valid = (n < N);

    // --- xe/ye (4 channels per thread) ---
    {
        float x0 = 0, x1 = 0, x2 = 0, y0 = 0, y1 = 0, y2 = 0;
        if (valid) {
            x0 = x[n*3+0]; x1 = x[n*3+1]; x2 = x[n*3+2];
            y0 = y[n*3+0]; y1 = y[n*3+1]; y2 = y[n*3+2];
        }
        #pragma unroll
        for (int ii = 0; ii < 4; ii++) {
            int i = part * 4 + ii;
            float w0 = __ldg(&peW[i]), w1 = __ldg(&peW[C_POS + i]), w2 = __ldg(&peW[2*C_POS + i]);
            float b = __ldg(&peb[i]);
            s_in[nl*SIN_S + i]      = fmaf(y0, w0, fmaf(y1, w1, fmaf(y2, w2, b)));
            s_in[nl*SIN_S + 32 + i] = fmaf(x0, w0, fmaf(x1, w1, fmaf(x2, w2, b)));
        }
    }
    __syncthreads();

    // --- Q, K, femb (8 outputs per thread, jb = part*8) ---
    float facc[8];
    {
        const int jb = part * 8;
        float qacc[8], kacc[8];
        #pragma unroll
        for (int jj = 0; jj < 8; jj++) {
            qacc[jj] = __ldg(&bq[jb + jj]);
            kacc[jj] = __ldg(&bk[jb + jj]);
            facc[jj] = __ldg(&liftb[jb + jj]);
        }
        #pragma unroll
        for (int i = 0; i < C_POS; i++) {
            float ye = s_in[nl*SIN_S + i];
            float xe = s_in[nl*SIN_S + 32 + i];
            #pragma unroll
            for (int j4 = 0; j4 < 2; j4++) {
                float4 wq = *(const float4*)&s_wt[i*64 + jb + 4*j4];
                float4 wk = *(const float4*)&s_wt[2048 + i*64 + jb + 4*j4];
                qacc[4*j4+0] = fmaf(ye, wq.x, qacc[4*j4+0]);
                qacc[4*j4+1] = fmaf(ye, wq.y, qacc[4*j4+1]);
                qacc[4*j4+2] = fmaf(ye, wq.z, qacc[4*j4+2]);
                qacc[4*j4+3] = fmaf(ye, wq.w, qacc[4*j4+3]);
                kacc[4*j4+0] = fmaf(xe, wk.x, kacc[4*j4+0]);
                kacc[4*j4+1] = fmaf(xe, wk.y, kacc[4*j4+1]);
                kacc[4*j4+2] = fmaf(xe, wk.z, kacc[4*j4+2]);
                kacc[4*j4+3] = fmaf(xe, wk.w, kacc[4*j4+3]);
            }
        }
        #pragma unroll 8
        for (int k = 0; k < C_F; k++) {
            float f = s_in[nl*SIN_S + 64 + k];
            #pragma unroll
            for (int j4 = 0; j4 < 2; j4++) {
                float4 wl = *(const float4*)&s_wt[4096 + k*64 + jb + 4*j4];
                facc[4*j4+0] = fmaf(f, wl.x, facc[4*j4+0]);
                facc[4*j4+1] = fmaf(f, wl.y, facc[4*j4+1]);
                facc[4*j4+2] = fmaf(f, wl.z, facc[4*j4+2]);
                facc[4*j4+3] = fmaf(f, wl.w, facc[4*j4+3]);
            }
        }
        if (valid) {
            *(float4*)&g_Q[(size_t)n*C_OUT + jb]     = make_float4(qacc[0], qacc[1], qacc[2], qacc[3]);
            *(float4*)&g_Q[(size_t)n*C_OUT + jb + 4] = make_float4(qacc[4], qacc[5], qacc[6], qacc[7]);
            *(float4*)&g_K[(size_t)n*C_OUT + jb]     = make_float4(kacc[0], kacc[1], kacc[2], kacc[3]);
            *(float4*)&g_K[(size_t)n*C_OUT + jb + 4] = make_float4(kacc[4], kacc[5], kacc[6], kacc[7]);
            *(float4*)&g_femb[(size_t)n*C_OUT + jb]     = make_float4(facc[0], facc[1], facc[2], facc[3]);
            *(float4*)&g_femb[(size_t)n*C_OUT + jb + 4] = make_float4(facc[4], facc[5], facc[6], facc[7]);
        }
    }

    // --- init out rows / denom ---
    #pragma unroll
    for (int it = 0; it < 2; it++) {
        int idx4 = tid + it * 512;
        int nn = n0 + (idx4 >> 4);
        if (nn < N)
            *(float4*)&out[(size_t)nn * C_OUT + (idx4 & 15) * 4] =
                make_float4(0.f, 0.f, 0.f, 0.f);
    }
    if (tid < 64 && n0 + tid < N) g_denom[n0 + tid] = 0.0f;
    __syncthreads();   // all femb-loop reads of s_in done before overwrite

    // --- overwrite fx region with femb ---
    {
        const int jb = part * 8;
        *(float4*)&s_in[nl*SIN_S + 64 + jb]     = make_float4(facc[0], facc[1], facc[2], facc[3]);
        *(float4*)&s_in[nl*SIN_S + 64 + jb + 4] = make_float4(facc[4], facc[5], facc[6], facc[7]);
    }
    __syncthreads();

    // --- repack s_in [64x128] -> s_inH fp16 pair layout ---
    #pragma unroll
    for (int it = 0; it < 2; it++) {
        int row = it*32 + w*2 + (lane >> 4);
        int li = lane & 15;
        const float* src = &s_in[row*SIN_S + li*8];
        float4 a0 = *(const float4*)src;
        float4 a1 = *(const float4*)(src + 4);
        unsigned base = (li >> 1) * RS + row * 8 + (li & 1);
        s_inH[base + 0] = packh2(a0.x, a0.y);
        s_inH[base + 2] = packh2(a0.z, a0.w);
        s_inH[base + 4] = packh2(a1.x, a1.y);
        s_inH[base + 6] = packh2(a1.z, a1.w);
    }
    cp_wait<0>();
    __syncthreads();

    // --- phase 2: in[64x128] @ W1[128x256] via fp16 mma ---
    const int wm = w & 1;
    const int wn = w >> 1;
    float cA[2][4][4], cB[2][4][4];
    #pragma unroll
    for (int mt = 0; mt < 2; mt++)
        #pragma unroll
        for (int nt = 0; nt < 4; nt++)
            #pragma unroll
            for (int i = 0; i < 4; i++) { cA[mt][nt][i] = 0.0f; cB[mt][nt][i] = 0.0f; }

    #pragma unroll
    for (int kg = 0; kg < 8; kg++) {
        unsigned a[2][4];
        #pragma unroll
        for (int mt = 0; mt < 2; mt++) {
            int row = wm*32 + mt*16 + g;
            uint2 lo = *(const uint2*)&s_inH[kg*RS + row*8 + 2*q];
            uint2 hi = *(const uint2*)&s_inH[kg*RS + (row+8)*8 + 2*q];
            a[mt][0] = lo.x; a[mt][1] = hi.x; a[mt][2] = lo.y; a[mt][3] = hi.y;
        }
        unsigned b[4][2];
        #pragma unroll
        for (int nt = 0; nt < 4; nt++) {
            int nn = wn*32 + nt*8 + g;
            uint2 bb = *(const uint2*)&w1h[kg*(H1*8) + nn*8 + 2*q];
            b[nt][0] = bb.x; b[nt][1] = bb.y;
        }
        if (kg < 2) {      // pass A: k 0..31 -> Ya
            #pragma unroll
            for (int mt = 0; mt < 2; mt++)
                #pragma unroll
                for (int nt = 0; nt < 4; nt++)
                    hmma(cA[mt][nt], a[mt], b[nt]);
        } else {           // pass B: k 32..127 -> XFc
            #pragma unroll
            for (int mt = 0; mt < 2; mt++)
                #pragma unroll
                for (int nt = 0; nt < 4; nt++)
                    hmma(cB[mt][nt], a[mt], b[nt]);
        }
    }
    __syncthreads();   // s_inH reads done; s_outU alias region free

    // --- epilogue A: Ya (half2 packed) -> s_outU -> g_YaH ---
    #pragma unroll
    for (int mt = 0; mt < 2; mt++) {
        #pragma unroll
        for (int nt = 0; nt < 4; nt++) {
            int cw = wn*16 + nt*4 + q;
            int r0 = wm*32 + mt*16 + g;
            s_outU[r0*SOUT_S + cw]     = packh2(cA[mt][nt][0], cA[mt][nt][1]);
            s_outU[(r0+8)*SOUT_S + cw] = packh2(cA[mt][nt][2], cA[mt][nt][3]);
        }
    }
    __syncthreads();
    #pragma unroll
    for (int it = 0; it < 4; it++) {
        int idx4 = tid + it * 512;
        int row = idx4 >> 5, c = idx4 & 31;
        uint4 v = *(const uint4*)&s_outU[row*SOUT_S + c*4];
        int nn = n0 + row;
        if (nn < N) ((uint4*)g_YaH)[(size_t)nn*32 + c] = v;
    }
    __syncthreads();

    // --- epilogue B: XFc + b1 (half2 packed) -> s_outU -> g_XFcH ---
    #pragma unroll
    for (int mt = 0; mt < 2; mt++) {
        #pragma unroll
        for (int nt = 0; nt < 4; nt++) {
            int cw = wn*16 + nt*4 + q;
            int col0 = 2*cw;
            int r0 = wm*32 + mt*16 + g;
            float bb0 = __ldg(&b1[col0]);
            float bb1 = __ldg(&b1[col0 + 1]);
            s_outU[r0*SOUT_S + cw]     = packh2(cB[mt][nt][0] + bb0, cB[mt][nt][1] + bb1);
            s_outU[(r0+8)*SOUT_S + cw] = packh2(cB[mt][nt][2] + bb0, cB[mt][nt][3] + bb1);
        }
    }
    __syncthreads();
    #pragma unroll
    for (int it = 0; it < 4; it++) {
        int idx4 = tid + it * 512;
        int row = idx4 >> 5, c = idx4 & 31;
        uint4 v = *(const uint4*)&s_outU[row*SOUT_S + c*4];
        int nn = n0 + row;
        if (nn < N) ((uint4*)g_XFcH)[(size_t)nn*32 + c] = v;
    }
}

// ---------------- kernel 3: scores + exp + warp-aggregated segment sum ------
__global__ void zscore_kernel(const int* __restrict__ src, const int* __restrict__ trg, int E) {
    int e = blockIdx.x * blockDim.x + threadIdx.x;
    const int lane = threadIdx.x & 31;
    bool valid = (e < E);
    int ec = valid ? e : (E - 1);
    int t = trg[ec], s = src[ec];

    const float4* q = (const float4*)(g_Q + (size_t)t * C_OUT);
    const float4* k = (const float4*)(g_K + (size_t)s * C_OUT);
    float sum = 0.0f;
    #pragma unroll
    for (int i = 0; i < C_OUT/4; i++) {
        float4 a = __ldg(&q[i]); float4 b = __ldg(&k[i]);
        sum = fmaf(a.x, b.x, sum);
        sum = fmaf(a.y, b.y, sum);
        sum = fmaf(a.z, b.z, sum);
        sum = fmaf(a.w, b.w, sum);
    }
    float z = valid ? __expf(sum * 0.125f) : 0.0f;
    if (valid) g_z[e] = z;

    // segmented suffix-sum over sorted t within the warp; run heads atomicAdd
    float acc = z;
    #pragma unroll
    for (int off = 1; off < 32; off <<= 1) {
        float v = __shfl_down_sync(0xFFFFFFFFu, acc, off);
        int  tv = __shfl_down_sync(0xFFFFFFFFu, t, off);
        if (lane + off < 32 && tv == t) acc += v;
    }
    int tprev = __shfl_up_sync(0xFFFFFFFFu, t, 1);
    if (lane == 0 || tprev != t) atomicAdd(&g_denom[t], acc);
}

// ---------------- kernel 4: persistent edge MLP ----------------
#define OFF_H2H   4096
#define OFF_W2H   8224
#define OFF_W3H   24608
#define OFF_ALPHA 28704
#define OFF_TRG   28768
#define OFF_SRC   28832
#define ESM_WORDS 28896
#define ESM_BYTES (ESM_WORDS * 4)
#define NTHR2 512
#define EGRID 296    // 2 CTAs x 148 SMs, all resident

__global__ void __launch_bounds__(NTHR2, 2) edge_kernel(
    const int* __restrict__ src, const int* __restrict__ trg,
    const float* __restrict__ b2, const float* __restrict__ b3,
    float* __restrict__ out, int E)
{
    extern __shared__ unsigned sm[];
    unsigned* h1h   = sm;
    unsigned* h2h   = sm + OFF_H2H;
    unsigned* w2h   = sm + OFF_W2H;
    unsigned* w3h   = sm + OFF_W3H;
    float*    s_alpha = (float*)(sm + OFF_ALPHA);
    int*      s_trg   = (int*)(sm + OFF_TRG);
    int*      s_src   = (int*)(sm + OFF_SRC);
    float*    s_out   = (float*)sm;   // [64][64], aliases h1h

    const int tid  = threadIdx.x;
    const int lane = tid & 31;
    const int w    = tid >> 5;
    const int q    = lane & 3;
    const int g    = lane >> 2;

    // --- stage ALL weights ONCE per CTA (persistent) ---
    {
        unsigned w2base = __cvta_generic_to_shared(w2h);
        unsigned w3base = __cvta_generic_to_shared(w3h);
        #pragma unroll
        for (int i = 0; i < 8; i++) {
            int v4 = tid + i * NTHR2;
            cp_async16(w2base + v4 * 16, (const uint4*)g_W2h + v4);
        }
        #pragma unroll
        for (int i = 0; i < 2; i++) {
            int v4 = tid + i * NTHR2;
            cp_async16(w3base + v4 * 16, (const uint4*)g_W3h + v4);
        }
        cp_commit();
    }

    bool first = true;
    const int ntiles = (E + 63) >> 6;

    for (int tile = blockIdx.x; tile < ntiles; tile += EGRID) {
        const int e0 = tile * 64;

        // --- metadata ---
        if (tid < 64) {
            int e = e0 + tid;
            int t, s; float al;
            if (e < E) { t = trg[e]; s = src[e]; al = g_z[e] / g_denom[t]; }
            else       { t = trg[E-1]; s = 0; al = 0.0f; }
            s_trg[tid] = t; s_src[tid] = s; s_alpha[tid] = al;
        }
        __syncthreads();

        // --- gather (half2 tables) + half2 gelu -> h1h (Ya dedup over runs) ---
        {
            int tprev = -1;
            uint4 ya4;
            #pragma unroll
            for (int rr = 0; rr < 4; rr++) {
                int row = w * 4 + rr;
                int t = s_trg[row], s = s_src[row];
                if (t != tprev) {
                    ya4 = __ldg((const uint4*)g_YaH + (size_t)t * 32 + lane);
                    tprev = t;
                }
                uint4 xf4 = __ldg((const uint4*)g_XFcH + (size_t)s * 32 + lane);
                __half2 p0 = gelu_h2(__hadd2(u2h(ya4.x), u2h(xf4.x)));
                __half2 p1 = gelu_h2(__hadd2(u2h(ya4.y), u2h(xf4.y)));
                __half2 p2 = gelu_h2(__hadd2(u2h(ya4.z), u2h(xf4.z)));
                __half2 p3 = gelu_h2(__hadd2(u2h(ya4.w), u2h(xf4.w)));
                unsigned base = (lane >> 1) * RS + row * 8 + (lane & 1);
                h1h[base + 0] = h2u(p0);
                h1h[base + 2] = h2u(p1);
                h1h[base + 4] = h2u(p2);
                h1h[base + 6] = h2u(p3);
            }
        }
        if (first) { cp_wait<0>(); first = false; }
        __syncthreads();

        // --- layer 2 GEMM: h1[64x256] @ W2[256x128], fp16 mma ---
        const int wm = w & 1;
        const int wn = w >> 1;
        float c2[2][2][4];
        #pragma unroll
        for (int mt = 0; mt < 2; mt++)
            #pragma unroll
            for (int nt = 0; nt < 2; nt++)
                #pragma unroll
                for (int i = 0; i < 4; i++) c2[mt][nt][i] = 0.0f;

        #pragma unroll
        for (int kg = 0; kg < 16; kg++) {
            unsigned a[2][4];
            #pragma unroll
            for (int mt = 0; mt < 2; mt++) {
                int row = wm*32 + mt*16 + g;
                uint2 lo = *(const uint2*)&h1h[kg*RS + row*8 + 2*q];
                uint2 hi = *(const uint2*)&h1h[kg*RS + (row+8)*8 + 2*q];
                a[mt][0] = lo.x; a[mt][1] = hi.x; a[mt][2] = lo.y; a[mt][3] = hi.y;
            }
            unsigned b[2][2];
            #pragma unroll
            for (int nt = 0; nt < 2; nt++) {
                int n = wn*16 + nt*8 + g;
                uint2 bb = *(const uint2*)&w2h[kg*(H2*8) + n*8 + 2*q];
                b[nt][0] = bb.x; b[nt][1] = bb.y;
            }
            #pragma unroll
            for (int mt = 0; mt < 2; mt++)
                #pragma unroll
                for (int nt = 0; nt < 2; nt++)
                    hmma(c2[mt][nt], a[mt], b[nt]);
        }
        __syncthreads();

        // --- layer 2 epilogue: bias + half2 gelu -> h2h ---
        #pragma unroll
        for (int mt = 0; mt < 2; mt++) {
            #pragma unroll
            for (int nt = 0; nt < 2; nt++) {
                int col0 = wn*16 + nt*8 + 2*q;
                int r0 = wm*32 + mt*16 + g;
                float bb0 = __ldg(&b2[col0]);
                float bb1 = __ldg(&b2[col0 + 1]);
                int kg2 = col0 >> 4;
                int pos = pairpos((col0 & 15) >> 1);
                __half2 lo = gelu_h2(u2h(packh2(c2[mt][nt][0] + bb0, c2[mt][nt][1] + bb1)));
                __half2 hi = gelu_h2(u2h(packh2(c2[mt][nt][2] + bb0, c2[mt][nt][3] + bb1)));
                h2h[kg2*RS + r0*8 + pos]     = h2u(lo);
                h2h[kg2*RS + (r0+8)*8 + pos] = h2u(hi);
            }
        }
        __syncthreads();

        // --- layer 3 GEMM: h2[64x128] @ W3[128x64], fp16 mma ---
        const int wm3 = w & 1;
        const int wn3 = w >> 1;
        float c3[2][4];
        #pragma unroll
        for (int mt = 0; mt < 2; mt++)
            #pragma unroll
            for (int i = 0; i < 4; i++) c3[mt][i] = 0.0f;

        #pragma unroll
        for (int kg = 0; kg < 8; kg++) {
            unsigned a[2][4];
            #pragma unroll
            for (int mt = 0; mt < 2; mt++) {
                int row = wm3*32 + mt*16 + g;
                uint2 lo = *(const uint2*)&h2h[kg*RS + row*8 + 2*q];
                uint2 hi = *(const uint2*)&h2h[kg*RS + (row+8)*8 + 2*q];
                a[mt][0] = lo.x; a[mt][1] = hi.x; a[mt][2] = lo.y; a[mt][3] = hi.y;
            }
            unsigned b[2];
            {
                int n = wn3*8 + g;
                uint2 bb = *(const uint2*)&w3h[kg*(C_OUT*8) + n*8 + 2*q];
                b[0] = bb.x; b[1] = bb.y;
            }
            hmma(c3[0], a[0], b);
            hmma(c3[1], a[1], b);
        }
        __syncthreads();

        // --- epilogue: alpha * (kout + b3) * f_src -> s_out ---
        {
            int col0 = wn3*8 + 2*q;
            float bb0 = __ldg(&b3[col0]);
            float bb1 = __ldg(&b3[col0 + 1]);
            #pragma unroll
            for (int mt = 0; mt < 2; mt++) {
                int r0 = wm3*32 + mt*16 + g;
                #pragma unroll
                for (int h = 0; h < 2; h++) {
                    int row = r0 + h*8;
                    float al = s_alpha[row];
                    int s = s_src[row];
                    float2 fs = __ldg((const float2*)(g_femb + (size_t)s * C_OUT + col0));
                    float kv0 = c3[mt][h*2 + 0] + bb0;
                    float kv1 = c3[mt][h*2 + 1] + bb1;
                    *(float2*)&s_out[row*64 + col0] =
                        make_float2(al * kv0 * fs.x, al * kv1 * fs.y);
                }
            }
        }
        __syncthreads();

        // --- run reduction (trg sorted) + atomic scatter ---
        for (int idx = tid; idx < 2048; idx += NTHR2) {
            int r = idx >> 5, col = (idx & 31) * 2;
            int t = s_trg[r];
            if (r > 0 && s_trg[r-1] == t) continue;
            float sx = 0.0f, sy = 0.0f;
            for (int rr = r; rr < 64 && s_trg[rr] == t; rr++) {
                float2 v = *(const float2*)&s_out[rr*64 + col];
                sx += v.x; sy += v.y;
            }
            atomicAdd(&out[(size_t)t*C_OUT + col],     sx);
            atomicAdd(&out[(size_t)t*C_OUT + col + 1], sy);
        }
        __syncthreads();   // s_out/h1h and metadata reads done before next tile
    }
}

// ---------------- launch ----------------
extern "C" void kernel_launch(void* const* d_in, const int* in_sizes, int n_in,
                              void* d_out, int out_size)
{
    const float* x     = (const float*)d_in[0];
    const float* y     = (const float*)d_in[1];
    const float* fx    = (const float*)d_in[2];
    const int*   src   = (const int*)d_in[3];
    const int*   trg   = (const int*)d_in[4];
    const float* peW   = (const float*)d_in[5];
    const float* peb   = (const float*)d_in[6];
    const float* Wq    = (const float*)d_in[7];
    const float* bq    = (const float*)d_in[8];
    const float* Wk    = (const float*)d_in[9];
    const float* bk    = (const float*)d_in[10];
    const float* liftW = (const float*)d_in[11];
    const float* liftb = (const float*)d_in[12];
    const float* W1    = (const float*)d_in[13];
    const float* b1    = (const float*)d_in[14];
    const float* W2    = (const float*)d_in[15];
    const float* b2    = (const float*)d_in[16];
    const float* W3    = (const float*)d_in[17];
    const float* b3    = (const float*)d_in[18];

    int N = in_sizes[0] / 3;
    int E = in_sizes[3];
    float* out = (float*)d_out;

    prep_kernel<<<64, 256>>>(W1, W2, W3);

    cudaFuncSetAttribute(node_fused,
                         cudaFuncAttributeMaxDynamicSharedMemorySize, NSM_BYTES);
    node_fused<<<(N + 63)/64, 512, NSM_BYTES>>>(x, y, fx, peW, peb, Wq, bq, Wk, bk,
                                                liftW, liftb, b1, out, N);
    zscore_kernel<<<(E + 255)/256, 256>>>(src, trg, E);

    cudaFuncSetAttribute(edge_kernel,
                         cudaFuncAttributeMaxDynamicSharedMemorySize, ESM_BYTES);
    edge_kernel<<<EGRID, NTHR2, ESM_BYTES>>>(src, trg, b2, b3, out, E);
}

// round 17
// speedup vs baseline: 1.1020x; 1.0093x over previous
#include <cuda_runtime.h>
#include <cuda_bf16.h>
#include <cuda_fp16.h>
#include <math.h>

// Problem constants
#define MAXN 20000
#define MAXE 480000
#define C_POS 32
#define C_OUT 64
#define C_F   64
#define H1    256
#define H2    128

// ---------------- scratch ----------------
__device__ float g_Q [MAXN * C_OUT];
__device__ float g_K [MAXN * C_OUT];
__device__ float g_femb[MAXN * C_OUT];
__device__ __align__(16) unsigned g_YaH [MAXN * 128];   // half2-packed Ya  [N][128]
__device__ __align__(16) unsigned g_XFcH[MAXN * 128];   // half2-packed XFc [N][128]
__device__ float g_z[MAXE];
__device__ float g_denom[MAXN];
__device__ __align__(16) unsigned g_W1h[8 * H1 * 8];    // fp16x2 pair-permuted
__device__ __align__(16) unsigned g_W2h[16 * H2 * 8];   // fp16x2 pair-permuted
__device__ __align__(16) unsigned g_W3h[8 * C_OUT * 8]; // fp16x2 pair-permuted

// ---------------- helpers ----------------
__device__ __forceinline__ unsigned h2u(__half2 h) { return *reinterpret_cast<unsigned*>(&h); }
__device__ __forceinline__ __half2 u2h(unsigned u) { return *reinterpret_cast<__half2*>(&u); }

// half2 gelu (tanh approx as v*sigmoid(2u)); saturates correctly at +-inf
__device__ __forceinline__ __half2 gelu_h2(__half2 v) {
    const __half2 one = __float2half2_rn(1.0f);
    const __half2 c1  = __float2half2_rn(0.044715f);
    const __half2 c2  = __float2half2_rn(2.3022085f);   // 2*0.7978845608*log2(e)
    __half2 v2 = __hmul2(v, v);
    __half2 w  = __hfma2(c1, v2, one);
    __half2 u  = __hmul2(__hmul2(c2, v), w);
    __half2 e  = h2exp2(u);
    __half2 r  = h2rcp(__hadd2(one, e));
    return __hfma2(__hneg2(v), r, v);   // v*(1 - 1/(1+2^u))
}

__device__ __forceinline__ int pairpos(int j) {
    return ((j & 3) << 1) | ((j >> 2) & 1);
}

__device__ __forceinline__ unsigned packh2(float lo, float hi) {
    unsigned r;
    asm("cvt.rn.f16x2.f32 %0, %1, %2;" : "=r"(r) : "f"(hi), "f"(lo));
    return r;
}

__device__ __forceinline__ void hmma(float* c, const unsigned* a, const unsigned* b) {
    asm volatile(
        "mma.sync.aligned.m16n8k16.row.col.f32.f16.f16.f32 "
        "{%0,%1,%2,%3},{%4,%5,%6,%7},{%8,%9},{%0,%1,%2,%3};\n"
        : "+f"(c[0]), "+f"(c[1]), "+f"(c[2]), "+f"(c[3])
        : "r"(a[0]), "r"(a[1]), "r"(a[2]), "r"(a[3]), "r"(b[0]), "r"(b[1]));
}

__device__ __forceinline__ void cp_async16(unsigned smem_addr, const void* gptr) {
    asm volatile("cp.async.cg.shared.global [%0], [%1], 16;\n"
                 :: "r"(smem_addr), "l"(gptr));
}
__device__ __forceinline__ void cp_commit() {
    asm volatile("cp.async.commit_group;\n");
}
template <int N>
__device__ __forceinline__ void cp_wait() {
    asm volatile("cp.async.wait_group %0;\n" :: "n"(N));
}

// ---------------- prep kernel: fp16 pair-permute W1/W2/W3 ----------------
__global__ void prep_kernel(const float* __restrict__ W1,
                            const float* __restrict__ W2,
                            const float* __restrict__ W3) {
    int i = blockIdx.x * blockDim.x + threadIdx.x;
    if (i < 16384) {                   // W1: 64 k-pairs x 256 n
        int kp = i >> 8, n = i & 255;
        g_W1h[(kp >> 3) * (H1 * 8) + n * 8 + pairpos(kp & 7)] =
            packh2(__ldg(&W1[(2*kp) * H1 + n]), __ldg(&W1[(2*kp + 1) * H1 + n]));
    }
    if (i < 16384) {                   // W2: 128 k-pairs x 128 n
        int kp = i >> 7, n = i & 127;
        g_W2h[(kp >> 3) * (H2 * 8) + n * 8 + pairpos(kp & 7)] =
            packh2(__ldg(&W2[(2*kp) * H2 + n]), __ldg(&W2[(2*kp + 1) * H2 + n]));
    }
    if (i < 4096) {                    // W3: 64 k-pairs x 64 n
        int kp = i >> 6, n = i & 63;
        g_W3h[(kp >> 3) * (C_OUT * 8) + n * 8 + pairpos(kp & 7)] =
            packh2(__ldg(&W3[(2*kp) * C_OUT + n]), __ldg(&W3[(2*kp + 1) * C_OUT + n]));
    }
}

// ============ kernel 2: fused node features + layer-1 factorization ========
// 64 nodes / block, 512 threads. Phase 2 uses fp16 mma; tables written half2.
#define SIN_S 132
#define RS 514
#define SOUT_S 132
#define NOFF_WT   8448
#define NOFF_INH  16640
#define NOFF_W1H  20752
#define NSM_WORDS 37136
#define NSM_BYTES (NSM_WORDS * 4)

__global__ void __launch_bounds__(512) node_fused(
    const float* __restrict__ x, const float* __restrict__ y,
    const float* __restrict__ fx,
    const float* __restrict__ peW, const float* __restrict__ peb,
    const float* __restrict__ Wq, const float* __restrict__ bq,
    const float* __restrict__ Wk, const float* __restrict__ bk,
    const float* __restrict__ liftW, const float* __restrict__ liftb,
    const float* __restrict__ b1,
    float* __restrict__ out, int N)
{
    extern __shared__ float ns[];
    float* s_in  = ns;
    float* s_wt  = ns + NOFF_WT;
    unsigned* s_outU = (unsigned*)ns;            // [64][SOUT_S] half2 words, alias
    unsigned* s_inH = (unsigned*)(ns + NOFF_INH);
    unsigned* w1h   = (unsigned*)(ns + NOFF_W1H);

    const int tid  = threadIdx.x;
    const int lane = tid & 31;
    const int w    = tid >> 5;        // 0..15
    const int q    = lane & 3;
    const int g    = lane >> 2;
    const int n0   = blockIdx.x * 64;

    // --- cp.async W1h (overlaps with all of phase 1) ---
    {
        unsigned w1base = __cvta_generic_to_shared(w1h);
        #pragma unroll
        for (int i = 0; i < 8; i++) {
            int v4 = tid + i * 512;
            cp_async16(w1base + v4 * 16, (const uint4*)g_W1h + v4);
        }
        cp_commit();
    }

    // --- stage Wq|Wk|liftW into s_wt ---
    *(float4*)&s_wt[tid * 4]          = __ldg((const float4*)Wq + tid);
    *(float4*)&s_wt[2048 + tid * 4]   = __ldg((const float4*)Wk + tid);
    *(float4*)&s_wt[4096 + tid * 4]   = __ldg((const float4*)liftW + tid);
    *(float4*)&s_wt[6144 + tid * 4]   = __ldg((const float4*)liftW + 512 + tid);

    // --- stage fx into s_in cols 64..127 ---
    #pragma unroll
    for (int it = 0; it < 2; it++) {
        int idx4 = tid + it * 512;
        int node = idx4 >> 4, c4 = (idx4 & 15) * 4;
        int n = n0 + node;
        float4 v = make_float4(0.f, 0.f, 0.f, 0.f);
        if (n < N) v = __ldg((const float4*)(fx + (size_t)n * C_F + c4));
        *(float4*)&s_in[node * SIN_S + 64 + c4] = v;
    }

    const int nl = tid >> 3, part = tid & 7;
    const int n = n0 + nl;
    const bool valid = (n < N);

    // --- xe/ye (4 channels per thread) ---
    {
        float x0 = 0, x1 = 0, x2 = 0, y0 = 0, y1 = 0, y2 = 0;
        if (valid) {
            x0 = x[n*3+0]; x1 = x[n*3+1]; x2 = x[n*3+2];
            y0 = y[n*3+0]; y1 = y[n*3+1]; y2 = y[n*3+2];
        }
        #pragma unroll
        for (int ii = 0; ii < 4; ii++) {
            int i = part * 4 + ii;
            float w0 = __ldg(&peW[i]), w1 = __ldg(&peW[C_POS + i]), w2 = __ldg(&peW[2*C_POS + i]);
            float b = __ldg(&peb[i]);
            s_in[nl*SIN_S + i]      = fmaf(y0, w0, fmaf(y1, w1, fmaf(y2, w2, b)));
            s_in[nl*SIN_S + 32 + i] = fmaf(x0, w0, fmaf(x1, w1, fmaf(x2, w2, b)));
        }
    }
    __syncthreads();

    // --- Q, K, femb (8 outputs per thread, jb = part*8) ---
    float facc[8];
    {
        const int jb = part * 8;
        float qacc[8], kacc[8];
        #pragma unroll
        for (int jj = 0; jj < 8; jj++) {
            qacc[jj] = __ldg(&bq[jb + jj]);
            kacc[jj] = __ldg(&bk[jb + jj]);
            facc[jj] = __ldg(&liftb[jb + jj]);
        }
        #pragma unroll
        for (int i = 0; i < C_POS; i++) {
            float ye = s_in[nl*SIN_S + i];
            float xe = s_in[nl*SIN_S + 32 + i];
            #pragma unroll
            for (int j4 = 0; j4 < 2; j4++) {
                float4 wq = *(const float4*)&s_wt[i*64 + jb + 4*j4];
                float4 wk = *(const float4*)&s_wt[2048 + i*64 + jb + 4*j4];
                qacc[4*j4+0] = fmaf(ye, wq.x, qacc[4*j4+0]);
                qacc[4*j4+1] = fmaf(ye, wq.y, qacc[4*j4+1]);
                qacc[4*j4+2] = fmaf(ye, wq.z, qacc[4*j4+2]);
                qacc[4*j4+3] = fmaf(ye, wq.w, qacc[4*j4+3]);
                kacc[4*j4+0] = fmaf(xe, wk.x, kacc[4*j4+0]);
                kacc[4*j4+1] = fmaf(xe, wk.y, kacc[4*j4+1]);
                kacc[4*j4+2] = fmaf(xe, wk.z, kacc[4*j4+2]);
                kacc[4*j4+3] = fmaf(xe, wk.w, kacc[4*j4+3]);
            }
        }
        #pragma unroll 8
        for (int k = 0; k < C_F; k++) {
            float f = s_in[nl*SIN_S + 64 + k];
            #pragma unroll
            for (int j4 = 0; j4 < 2; j4++) {
                float4 wl = *(const float4*)&s_wt[4096 + k*64 + jb + 4*j4];
                facc[4*j4+0] = fmaf(f, wl.x, facc[4*j4+0]);
                facc[4*j4+1] = fmaf(f, wl.y, facc[4*j4+1]);
                facc[4*j4+2] = fmaf(f, wl.z, facc[4*j4+2]);
                facc[4*j4+3] = fmaf(f, wl.w, facc[4*j4+3]);
            }
        }
        if (valid) {
            *(float4*)&g_Q[(size_t)n*C_OUT + jb]     = make_float4(qacc[0], qacc[1], qacc[2], qacc[3]);
            *(float4*)&g_Q[(size_t)n*C_OUT + jb + 4] = make_float4(qacc[4], qacc[5], qacc[6], qacc[7]);
            *(float4*)&g_K[(size_t)n*C_OUT + jb]     = make_float4(kacc[0], kacc[1], kacc[2], kacc[3]);
            *(float4*)&g_K[(size_t)n*C_OUT + jb + 4] = make_float4(kacc[4], kacc[5], kacc[6], kacc[7]);
            *(float4*)&g_femb[(size_t)n*C_OUT + jb]     = make_float4(facc[0], facc[1], facc[2], facc[3]);
            *(float4*)&g_femb[(size_t)n*C_OUT + jb + 4] = make_float4(facc[4], facc[5], facc[6], facc[7]);
        }
    }

    // --- init out rows / denom ---
    #pragma unroll
    for (int it = 0; it < 2; it++) {
        int idx4 = tid + it * 512;
        int nn = n0 + (idx4 >> 4);
        if (nn < N)
            *(float4*)&out[(size_t)nn * C_OUT + (idx4 & 15) * 4] =
                make_float4(0.f, 0.f, 0.f, 0.f);
    }
    if (tid < 64 && n0 + tid < N) g_denom[n0 + tid] = 0.0f;
    __syncthreads();   // all femb-loop reads of s_in done before overwrite

    // --- overwrite fx region with femb ---
    {
        const int jb = part * 8;
        *(float4*)&s_in[nl*SIN_S + 64 + jb]     = make_float4(facc[0], facc[1], facc[2], facc[3]);
        *(float4*)&s_in[nl*SIN_S + 64 + jb + 4] = make_float4(facc[4], facc[5], facc[6], facc[7]);
    }
    __syncthreads();

    // --- repack s_in [64x128] -> s_inH fp16 pair layout ---
    #pragma unroll
    for (int it = 0; it < 2; it++) {
        int row = it*32 + w*2 + (lane >> 4);
        int li = lane & 15;
        const float* src = &s_in[row*SIN_S + li*8];
        float4 a0 = *(const float4*)src;
        float4 a1 = *(const float4*)(src + 4);
        unsigned base = (li >> 1) * RS + row * 8 + (li & 1);
        s_inH[base + 0] = packh2(a0.x, a0.y);
        s_inH[base + 2] = packh2(a0.z, a0.w);
        s_inH[base + 4] = packh2(a1.x, a1.y);
        s_inH[base + 6] = packh2(a1.z, a1.w);
    }
    cp_wait<0>();
    __syncthreads();

    // --- phase 2: in[64x128] @ W1[128x256] via fp16 mma ---
    const int wm = w & 1;
    const int wn = w >> 1;
    float cA[2][4][4], cB[2][4][4];
    #pragma unroll
    for (int mt = 0; mt < 2; mt++)
        #pragma unroll
        for (int nt = 0; nt < 4; nt++)
            #pragma unroll
            for (int i = 0; i < 4; i++) { cA[mt][nt][i] = 0.0f; cB[mt][nt][i] = 0.0f; }

    #pragma unroll
    for (int kg = 0; kg < 8; kg++) {
        unsigned a[2][4];
        #pragma unroll
        for (int mt = 0; mt < 2; mt++) {
            int row = wm*32 + mt*16 + g;
            uint2 lo = *(const uint2*)&s_inH[kg*RS + row*8 + 2*q];
            uint2 hi = *(const uint2*)&s_inH[kg*RS + (row+8)*8 + 2*q];
            a[mt][0] = lo.x; a[mt][1] = hi.x; a[mt][2] = lo.y; a[mt][3] = hi.y;
        }
        unsigned b[4][2];
        #pragma unroll
        for (int nt = 0; nt < 4; nt++) {
            int nn = wn*32 + nt*8 + g;
            uint2 bb = *(const uint2*)&w1h[kg*(H1*8) + nn*8 + 2*q];
            b[nt][0] = bb.x; b[nt][1] = bb.y;
        }
        if (kg < 2) {      // pass A: k 0..31 -> Ya
            #pragma unroll
            for (int mt = 0; mt < 2; mt++)
                #pragma unroll
                for (int nt = 0; nt < 4; nt++)
                    hmma(cA[mt][nt], a[mt], b[nt]);
        } else {           // pass B: k 32..127 -> XFc
            #pragma unroll
            for (int mt = 0; mt < 2; mt++)
                #pragma unroll
                for (int nt = 0; nt < 4; nt++)
                    hmma(cB[mt][nt], a[mt], b[nt]);
        }
    }
    __syncthreads();   // s_inH reads done; s_outU alias region free

    // --- epilogue A: Ya (half2 packed) -> s_outU -> g_YaH ---
    #pragma unroll
    for (int mt = 0; mt < 2; mt++) {
        #pragma unroll
        for (int nt = 0; nt < 4; nt++) {
            int cw = wn*16 + nt*4 + q;
            int r0 = wm*32 + mt*16 + g;
            s_outU[r0*SOUT_S + cw]     = packh2(cA[mt][nt][0], cA[mt][nt][1]);
            s_outU[(r0+8)*SOUT_S + cw] = packh2(cA[mt][nt][2], cA[mt][nt][3]);
        }
    }
    __syncthreads();
    #pragma unroll
    for (int it = 0; it < 4; it++) {
        int idx4 = tid + it * 512;
        int row = idx4 >> 5, c = idx4 & 31;
        uint4 v = *(const uint4*)&s_outU[row*SOUT_S + c*4];
        int nn = n0 + row;
        if (nn < N) ((uint4*)g_YaH)[(size_t)nn*32 + c] = v;
    }
    __syncthreads();

    // --- epilogue B: XFc + b1 (half2 packed) -> s_outU -> g_XFcH ---
    #pragma unroll
    for (int mt = 0; mt < 2; mt++) {
        #pragma unroll
        for (int nt = 0; nt < 4; nt++) {
            int cw = wn*16 + nt*4 + q;
            int col0 = 2*cw;
            int r0 = wm*32 + mt*16 + g;
            float bb0 = __ldg(&b1[col0]);
            float bb1 = __ldg(&b1[col0 + 1]);
            s_outU[r0*SOUT_S + cw]     = packh2(cB[mt][nt][0] + bb0, cB[mt][nt][1] + bb1);
            s_outU[(r0+8)*SOUT_S + cw] = packh2(cB[mt][nt][2] + bb0, cB[mt][nt][3] + bb1);
        }
    }
    __syncthreads();
    #pragma unroll
    for (int it = 0; it < 4; it++) {
        int idx4 = tid + it * 512;
        int row = idx4 >> 5, c = idx4 & 31;
        uint4 v = *(const uint4*)&s_outU[row*SOUT_S + c*4];
        int nn = n0 + row;
        if (nn < N) ((uint4*)g_XFcH)[(size_t)nn*32 + c] = v;
    }
}

// ---------------- kernel 3: scores + exp + warp-aggregated segment sum ------
__global__ void zscore_kernel(const int* __restrict__ src, const int* __restrict__ trg, int E) {
    int e = blockIdx.x * blockDim.x + threadIdx.x;
    const int lane = threadIdx.x & 31;
    bool valid = (e < E);
    int ec = valid ? e : (E - 1);
    int t = trg[ec], s = src[ec];

    const float4* q = (const float4*)(g_Q + (size_t)t * C_OUT);
    const float4* k = (const float4*)(g_K + (size_t)s * C_OUT);
    float sum = 0.0f;
    #pragma unroll
    for (int i = 0; i < C_OUT/4; i++) {
        float4 a = __ldg(&q[i]); float4 b = __ldg(&k[i]);
        sum = fmaf(a.x, b.x, sum);
        sum = fmaf(a.y, b.y, sum);
        sum = fmaf(a.z, b.z, sum);
        sum = fmaf(a.w, b.w, sum);
    }
    float z = valid ? __expf(sum * 0.125f) : 0.0f;
    if (valid) g_z[e] = z;

    // segmented suffix-sum over sorted t within the warp; run heads atomicAdd
    float acc = z;
    #pragma unroll
    for (int off = 1; off < 32; off <<= 1) {
        float v = __shfl_down_sync(0xFFFFFFFFu, acc, off);
        int  tv = __shfl_down_sync(0xFFFFFFFFu, t, off);
        if (lane + off < 32 && tv == t) acc += v;
    }
    int tprev = __shfl_up_sync(0xFFFFFFFFu, t, 1);
    if (lane == 0 || tprev != t) atomicAdd(&g_denom[t], acc);
}

// ---------------- kernel 4: persistent edge MLP ----------------
#define OFF_H2H   4096
#define OFF_W2H   8224
#define OFF_W3H   24608
#define OFF_ALPHA 28704
#define OFF_TRG   28768
#define OFF_SRC   28832
#define ESM_WORDS 28896
#define ESM_BYTES (ESM_WORDS * 4)
#define NTHR2 512
#define EGRID 296    // 2 CTAs x 148 SMs, all resident

__global__ void __launch_bounds__(NTHR2, 2) edge_kernel(
    const int* __restrict__ src, const int* __restrict__ trg,
    const float* __restrict__ b2, const float* __restrict__ b3,
    float* __restrict__ out, int E)
{
    extern __shared__ unsigned sm[];
    unsigned* h1h   = sm;
    unsigned* h2h   = sm + OFF_H2H;
    unsigned* w2h   = sm + OFF_W2H;
    unsigned* w3h   = sm + OFF_W3H;
    float*    s_alpha = (float*)(sm + OFF_ALPHA);
    int*      s_trg   = (int*)(sm + OFF_TRG);
    int*      s_src   = (int*)(sm + OFF_SRC);
    float*    s_out   = (float*)sm;   // [64][64], aliases h1h

    const int tid  = threadIdx.x;
    const int lane = tid & 31;
    const int w    = tid >> 5;
    const int q    = lane & 3;
    const int g    = lane >> 2;

    // --- stage ALL weights ONCE per CTA (persistent) ---
    {
        unsigned w2base = __cvta_generic_to_shared(w2h);
        unsigned w3base = __cvta_generic_to_shared(w3h);
        #pragma unroll
        for (int i = 0; i < 8; i++) {
            int v4 = tid + i * NTHR2;
            cp_async16(w2base + v4 * 16, (const uint4*)g_W2h + v4);
        }
        #pragma unroll
        for (int i = 0; i < 2; i++) {
            int v4 = tid + i * NTHR2;
            cp_async16(w3base + v4 * 16, (const uint4*)g_W3h + v4);
        }
        cp_commit();
    }

    bool first = true;
    const int ntiles = (E + 63) >> 6;

    for (int tile = blockIdx.x; tile < ntiles; tile += EGRID) {
        const int e0 = tile * 64;

        // --- per-warp metadata: lanes 0..3 load this warp's 4 rows, shfl-bcast ---
        int mt_t = 0, mt_s = 0; float mt_al = 0.0f;
        if (lane < 4) {
            int e = e0 + w * 4 + lane;
            if (e < E) {
                mt_t = trg[e]; mt_s = src[e];
                mt_al = g_z[e] / g_denom[mt_t];
            } else {
                mt_t = trg[E-1]; mt_s = 0; mt_al = 0.0f;
            }
            int row = w * 4 + lane;
            s_trg[row] = mt_t; s_src[row] = mt_s; s_alpha[row] = mt_al;
        }

        // --- gather (half2 tables) + half2 gelu -> h1h (Ya dedup over runs) ---
        {
            int tprev = -1;
            uint4 ya4;
            #pragma unroll
            for (int rr = 0; rr < 4; rr++) {
                int row = w * 4 + rr;
                int t = __shfl_sync(0xFFFFFFFFu, mt_t, rr);
                int s = __shfl_sync(0xFFFFFFFFu, mt_s, rr);
                if (t != tprev) {
                    ya4 = __ldg((const uint4*)g_YaH + (size_t)t * 32 + lane);
                    tprev = t;
                }
                uint4 xf4 = __ldg((const uint4*)g_XFcH + (size_t)s * 32 + lane);
                __half2 p0 = gelu_h2(__hadd2(u2h(ya4.x), u2h(xf4.x)));
                __half2 p1 = gelu_h2(__hadd2(u2h(ya4.y), u2h(xf4.y)));
                __half2 p2 = gelu_h2(__hadd2(u2h(ya4.z), u2h(xf4.z)));
                __half2 p3 = gelu_h2(__hadd2(u2h(ya4.w), u2h(xf4.w)));
                unsigned base = (lane >> 1) * RS + row * 8 + (lane & 1);
                h1h[base + 0] = h2u(p0);
                h1h[base + 2] = h2u(p1);
                h1h[base + 4] = h2u(p2);
                h1h[base + 6] = h2u(p3);
            }
        }
        if (first) { cp_wait<0>(); first = false; }
        __syncthreads();   // publishes h1h AND s_trg/s_src/s_alpha

        // --- layer 2 GEMM: h1[64x256] @ W2[256x128], fp16 mma ---
        const int wm = w & 1;
        const int wn = w >> 1;
        float c2[2][2][4];
        #pragma unroll
        for (int mt = 0; mt < 2; mt++)
            #pragma unroll
            for (int nt = 0; nt < 2; nt++)
                #pragma unroll
                for (int i = 0; i < 4; i++) c2[mt][nt][i] = 0.0f;

        #pragma unroll
        for (int kg = 0; kg < 16; kg++) {
            unsigned a[2][4];
            #pragma unroll
            for (int mt = 0; mt < 2; mt++) {
                int row = wm*32 + mt*16 + g;
                uint2 lo = *(const uint2*)&h1h[kg*RS + row*8 + 2*q];
                uint2 hi = *(const uint2*)&h1h[kg*RS + (row+8)*8 + 2*q];
                a[mt][0] = lo.x; a[mt][1] = hi.x; a[mt][2] = lo.y; a[mt][3] = hi.y;
            }
            unsigned b[2][2];
            #pragma unroll
            for (int nt = 0; nt < 2; nt++) {
                int n = wn*16 + nt*8 + g;
                uint2 bb = *(const uint2*)&w2h[kg*(H2*8) + n*8 + 2*q];
                b[nt][0] = bb.x; b[nt][1] = bb.y;
            }
            #pragma unroll
            for (int mt = 0; mt < 2; mt++)
                #pragma unroll
                for (int nt = 0; nt < 2; nt++)
                    hmma(c2[mt][nt], a[mt], b[nt]);
        }
        __syncthreads();

        // --- layer 2 epilogue: bias + half2 gelu -> h2h ---
        #pragma unroll
        for (int mt = 0; mt < 2; mt++) {
            #pragma unroll
            for (int nt = 0; nt < 2; nt++) {
                int col0 = wn*16 + nt*8 + 2*q;
                int r0 = wm*32 + mt*16 + g;
                float bb0 = __ldg(&b2[col0]);
                float bb1 = __ldg(&b2[col0 + 1]);
                int kg2 = col0 >> 4;
                int pos = pairpos((col0 & 15) >> 1);
                __half2 lo = gelu_h2(u2h(packh2(c2[mt][nt][0] + bb0, c2[mt][nt][1] + bb1)));
                __half2 hi = gelu_h2(u2h(packh2(c2[mt][nt][2] + bb0, c2[mt][nt][3] + bb1)));
                h2h[kg2*RS + r0*8 + pos]     = h2u(lo);
                h2h[kg2*RS + (r0+8)*8 + pos] = h2u(hi);
            }
        }
        __syncthreads();

        // --- layer 3 GEMM: h2[64x128] @ W3[128x64], fp16 mma ---
        const int wm3 = w & 1;
        const int wn3 = w >> 1;
        float c3[2][4];
        #pragma unroll
        for (int mt = 0; mt < 2; mt++)
            #pragma unroll
            for (int i = 0; i < 4; i++) c3[mt][i] = 0.0f;

        #pragma unroll
        for (int kg = 0; kg < 8; kg++) {
            unsigned a[2][4];
            #pragma unroll
            for (int mt = 0; mt < 2; mt++) {
                int row = wm3*32 + mt*16 + g;
                uint2 lo = *(const uint2*)&h2h[kg*RS + row*8 + 2*q];
                uint2 hi = *(const uint2*)&h2h[kg*RS + (row+8)*8 + 2*q];
                a[mt][0] = lo.x; a[mt][1] = hi.x; a[mt][2] = lo.y; a[mt][3] = hi.y;
            }
            unsigned b[2];
            {
                int n = wn3*8 + g;
                uint2 bb = *(const uint2*)&w3h[kg*(C_OUT*8) + n*8 + 2*q];
                b[0] = bb.x; b[1] = bb.y;
            }
            hmma(c3[0], a[0], b);
            hmma(c3[1], a[1], b);
        }
        __syncthreads();

        // --- epilogue: alpha * (kout + b3) * f_src -> s_out ---
        {
            int col0 = wn3*8 + 2*q;
            float bb0 = __ldg(&b3[col0]);
            float bb1 = __ldg(&b3[col0 + 1]);
            #pragma unroll
            for (int mt = 0; mt < 2; mt++) {
                int r0 = wm3*32 + mt*16 + g;
                #pragma unroll
                for (int h = 0; h < 2; h++) {
                    int row = r0 + h*8;
                    float al = s_alpha[row];
                    int s = s_src[row];
                    float2 fs = __ldg((const float2*)(g_femb + (size_t)s * C_OUT + col0));
                    float kv0 = c3[mt][h*2 + 0] + bb0;
                    float kv1 = c3[mt][h*2 + 1] + bb1;
                    *(float2*)&s_out[row*64 + col0] =
                        make_float2(al * kv0 * fs.x, al * kv1 * fs.y);
                }
            }
        }
        __syncthreads();

        // --- run reduction (trg sorted) + atomic scatter ---
        for (int idx = tid; idx < 2048; idx += NTHR2) {
            int r = idx >> 5, col = (idx & 31) * 2;
            int t = s_trg[r];
            if (r > 0 && s_trg[r-1] == t) continue;
            float sx = 0.0f, sy = 0.0f;
            for (int rr = r; rr < 64 && s_trg[rr] == t; rr++) {
                float2 v = *(const float2*)&s_out[rr*64 + col];
                sx += v.x; sy += v.y;
            }
            atomicAdd(&out[(size_t)t*C_OUT + col],     sx);
            atomicAdd(&out[(size_t)t*C_OUT + col + 1], sy);
        }
        __syncthreads();   // s_out/h1h and s_* reads done before next tile
    }
}

// ---------------- launch ----------------
extern "C" void kernel_launch(void* const* d_in, const int* in_sizes, int n_in,
                              void* d_out, int out_size)
{
    const float* x     = (const float*)d_in[0];
    const float* y     = (const float*)d_in[1];
    const float* fx    = (const float*)d_in[2];
    const int*   src   = (const int*)d_in[3];
    const int*   trg   = (const int*)d_in[4];
    const float* peW   = (const float*)d_in[5];
    const float* peb   = (const float*)d_in[6];
    const float* Wq    = (const float*)d_in[7];
    const float* bq    = (const float*)d_in[8];
    const float* Wk    = (const float*)d_in[9];
    const float* bk    = (const float*)d_in[10];
    const float* liftW = (const float*)d_in[11];
    const float* liftb = (const float*)d_in[12];
    const float* W1    = (const float*)d_in[13];
    const float* b1    = (const float*)d_in[14];
    const float* W2    = (const float*)d_in[15];
    const float* b2    = (const float*)d_in[16];
    const float* W3    = (const float*)d_in[17];
    const float* b3    = (const float*)d_in[18];

    int N = in_sizes[0] / 3;
    int E = in_sizes[3];
    float* out = (float*)d_out;

    prep_kernel<<<64, 256>>>(W1, W2, W3);

    cudaFuncSetAttribute(node_fused,
                         cudaFuncAttributeMaxDynamicSharedMemorySize, NSM_BYTES);
    node_fused<<<(N + 63)/64, 512, NSM_BYTES>>>(x, y, fx, peW, peb, Wq, bq, Wk, bk,
                                                liftW, liftb, b1, out, N);
    zscore_kernel<<<(E + 255)/256, 256>>>(src, trg, E);

    cudaFuncSetAttribute(edge_kernel,
                         cudaFuncAttributeMaxDynamicSharedMemorySize, ESM_BYTES);
    edge_kernel<<<EGRID, NTHR2, ESM_BYTES>>>(src, trg, b2, b3, out, E);
}